// round 12
// baseline (speedup 1.0000x reference)
#include <cuda_runtime.h>
#include <cuda_bf16.h>
#include <cstdint>

// ---------------------------------------------------------------------------
// MultiHeadCrossAttn on sm_100 (base target; legacy mma.sync path).
//  Pre-split: fp32 -> bf16 hi/lo elementwise (h, c, Wq, Wkv, Wo).
//  GEMMs:     pure-bf16 3-pass mma GEMM, 256x128 CTA tile, 512 threads,
//             cp.async 2-stage pipeline (R9 dual-live fragment loop).
//  Attention: mma flash attention (bf16x3), 2 CTA/SM, x4 K-LDSM.
//  LN:        fp32 two-pass.
// ---------------------------------------------------------------------------

#define NH 16
#define DH 64
#define DM 1024
#define QL 1024
#define KVL 2048
#define BB 4
#define QROWS (QL*BB)     // 4096
#define KVROWS (KVL*BB)   // 8192
#define ATTN_SCALE 0.125f

typedef unsigned short ushort_t;

// pre-split inputs
__device__ ushort_t g_hh [QROWS * DM];
__device__ ushort_t g_hl [QROWS * DM];
__device__ ushort_t g_ch [KVROWS * DM];
__device__ ushort_t g_cl [KVROWS * DM];
__device__ ushort_t g_Wqh [DM * DM];
__device__ ushort_t g_Wql [DM * DM];
__device__ ushort_t g_Wkvh[2 * DM * DM];
__device__ ushort_t g_Wkvl[2 * DM * DM];
__device__ ushort_t g_Woh [DM * DM];
__device__ ushort_t g_Wol [DM * DM];
// intermediates
__device__ ushort_t g_Qh [QROWS * DM];        // prescaled by 0.125
__device__ ushort_t g_Ql [QROWS * DM];
__device__ ushort_t g_KVh[KVROWS * 2 * DM];   // K cols 0-1023, V cols 1024-2047
__device__ ushort_t g_KVl[KVROWS * 2 * DM];
__device__ ushort_t g_AVh[QROWS * DM];
__device__ ushort_t g_AVl[QROWS * DM];
__device__ float    g_Y  [QROWS * DM];

// ------------------------------- helpers -----------------------------------
__device__ __forceinline__ uint32_t smem_u32(const void* p) {
    uint32_t a;
    asm("{ .reg .u64 t; cvta.to.shared.u64 t, %1; cvt.u32.u64 %0, t; }"
        : "=r"(a) : "l"(p));
    return a;
}
__device__ __forceinline__ void ldsm_x4(uint32_t& r0, uint32_t& r1,
                                        uint32_t& r2, uint32_t& r3, uint32_t addr) {
    asm volatile("ldmatrix.sync.aligned.m8n8.x4.shared.b16 {%0,%1,%2,%3}, [%4];"
                 : "=r"(r0), "=r"(r1), "=r"(r2), "=r"(r3) : "r"(addr));
}
__device__ __forceinline__ void ldsm_x4t(uint32_t& r0, uint32_t& r1,
                                         uint32_t& r2, uint32_t& r3, uint32_t addr) {
    asm volatile("ldmatrix.sync.aligned.m8n8.x4.trans.shared.b16 {%0,%1,%2,%3}, [%4];"
                 : "=r"(r0), "=r"(r1), "=r"(r2), "=r"(r3) : "r"(addr));
}
__device__ __forceinline__ void mma16816(float* c, const uint32_t* a, const uint32_t* b) {
    asm volatile("mma.sync.aligned.m16n8k16.row.col.f32.bf16.bf16.f32 "
                 "{%0,%1,%2,%3}, {%4,%5,%6,%7}, {%8,%9}, {%0,%1,%2,%3};"
                 : "+f"(c[0]), "+f"(c[1]), "+f"(c[2]), "+f"(c[3])
                 : "r"(a[0]), "r"(a[1]), "r"(a[2]), "r"(a[3]),
                   "r"(b[0]), "r"(b[1]));
}
__device__ __forceinline__ void split2(float x, float y, uint32_t& hi, uint32_t& lo) {
    __nv_bfloat16 hx = __float2bfloat16_rn(x);
    __nv_bfloat16 hy = __float2bfloat16_rn(y);
    float lxf = x - __bfloat162float(hx);
    float lyf = y - __bfloat162float(hy);
    __nv_bfloat16 lx = __float2bfloat16_rn(lxf);
    __nv_bfloat16 ly = __float2bfloat16_rn(lyf);
    hi = ((uint32_t)__bfloat16_as_ushort(hy) << 16) | __bfloat16_as_ushort(hx);
    lo = ((uint32_t)__bfloat16_as_ushort(ly) << 16) | __bfloat16_as_ushort(lx);
}
__device__ __forceinline__ void cp16(uint32_t saddr, const void* g) {
    asm volatile("cp.async.cg.shared.global [%0], [%1], 16;"
                 :: "r"(saddr), "l"(g));
}
#define CP_COMMIT() asm volatile("cp.async.commit_group;" ::: "memory")
#define CP_WAIT0()  asm volatile("cp.async.wait_group 0;" ::: "memory")
#define CP_WAIT1()  asm volatile("cp.async.wait_group 1;" ::: "memory")

// ---------------------------------------------------------------------------
// split: fp32 -> bf16 hi/lo
// ---------------------------------------------------------------------------
__global__ __launch_bounds__(256) void split_kernel(
    const float* __restrict__ X, ushort_t* __restrict__ Xh,
    ushort_t* __restrict__ Xl, int n)
{
    int idx = (blockIdx.x * 256 + threadIdx.x) * 4;
    if (idx >= n) return;
    float4 v = *(const float4*)(X + idx);
    uint32_t h0, l0, h1, l1;
    split2(v.x, v.y, h0, l0);
    split2(v.z, v.w, h1, l1);
    uint2 hv; hv.x = h0; hv.y = h1;
    uint2 lv; lv.x = l0; lv.y = l1;
    *(uint2*)(Xh + idx) = hv;
    *(uint2*)(Xl + idx) = lv;
}

// ---------------------------------------------------------------------------
// Pure-bf16 3-pass GEMM (NT): C = A[M,K] * B[N,K]^T, A/B pre-split hi/lo.
// CTA 256x128, BK=32, 512 threads (16 warps, 4x4 grid, warp tile 64x32),
// 2-stage cp.async pipeline. Smem rows: 32 bf16 = 64B + 16 pad = 80B.
// SPLIT=1: outputs bf16 hi/lo (scaled). SPLIT=0: fp32 + residual.
// ---------------------------------------------------------------------------
#define ROWB  80
#define AR2   20480              // 256 rows * 80B (A array, one precision)
#define BR2   10240              // 128 rows * 80B (B array, one precision)
#define STAGE2 (2*AR2 + 2*BR2)   // 61440: Ah | Al | Bh | Bl
#define GEMM_SMEM (2*STAGE2)     // 122880

template<int SPLIT>
__global__ __launch_bounds__(512, 1) void mma_gemm(
    const ushort_t* __restrict__ Ah_g, const ushort_t* __restrict__ Al_g,
    const ushort_t* __restrict__ Bh_g, const ushort_t* __restrict__ Bl_g,
    const float* __restrict__ R, float* __restrict__ C,
    ushort_t* __restrict__ Ch, ushort_t* __restrict__ Cl,
    float oscale, int M, int N, int K)
{
    extern __shared__ __align__(128) char sm[];
    const uint32_t sb = smem_u32(sm);
    const int tid = threadIdx.x;
    const int wid = tid >> 5, lane = tid & 31;
    const int m0 = blockIdx.y * 256, n0 = blockIdx.x * 128;
    const int wm = wid & 3, wn = wid >> 2;   // 4x4 warp grid: tile (wm*64, wn*32)

    float acc[4][4][4];
#pragma unroll
    for (int mi = 0; mi < 4; mi++)
#pragma unroll
        for (int nj = 0; nj < 4; nj++)
#pragma unroll
            for (int e = 0; e < 4; e++) acc[mi][nj][e] = 0.f;

    const int l8   = lane & 7;
    const int arow = ((lane >> 3) & 1) * 8 + l8;
    const int acol = ((lane >> 4) & 1) * 16;
    // x4 B addressing: lane groups 0-7/8-15 -> n-tile0 (k0/k8), 16-31 -> n-tile1
    const int b4row = ((lane >> 4) & 1) * 8 + l8;
    const int b4col = ((lane >> 3) & 1) * 16;

    const int nchunks = K >> 5;

    // issue stage kc into buffer kc&1
    // A: 1024 16B-chunks per array (256 rows x 4), 2/thread; B: 512, 1/thread.
    auto issue = [&](int kc) {
        const int kk = kc << 5;
        const uint32_t sbase = sb + (uint32_t)(kc & 1) * STAGE2;
#pragma unroll
        for (int u = 0; u < 2; u++) {
            int cid = tid * 2 + u;           // 0..1023
            int row = cid >> 2, c16 = cid & 3;
            uint32_t so = sbase + (uint32_t)row * ROWB + c16 * 16;
            size_t ao = (size_t)(m0 + row) * K + kk + c16 * 8;
            cp16(so,        Ah_g + ao);
            cp16(so + AR2,  Al_g + ao);
        }
        {
            int cid = tid;                   // 0..511
            int row = cid >> 2, c16 = cid & 3;
            uint32_t so = sbase + 2*AR2 + (uint32_t)row * ROWB + c16 * 16;
            size_t bo = (size_t)(n0 + row) * K + kk + c16 * 8;
            cp16(so,        Bh_g + bo);
            cp16(so + BR2,  Bl_g + bo);
        }
        CP_COMMIT();
    };

    issue(0);

    for (int kc = 0; kc < nchunks; kc++) {
        if (kc + 1 < nchunks) { issue(kc + 1); CP_WAIT1(); }
        else                  { CP_WAIT0(); }
        __syncthreads();

        const uint32_t abase = sb + (uint32_t)(kc & 1) * STAGE2;
        const uint32_t bbase = abase + 2 * AR2;
#pragma unroll
        for (int s = 0; s < 2; s++) {
            uint32_t bhf[4][2], blf[4][2];
#pragma unroll
            for (int njp = 0; njp < 2; njp++) {
                uint32_t baddr = bbase + (uint32_t)(wn*32 + njp*16 + b4row) * ROWB
                               + s*32 + b4col;
                ldsm_x4(bhf[2*njp][0], bhf[2*njp][1],
                        bhf[2*njp+1][0], bhf[2*njp+1][1], baddr);
                ldsm_x4(blf[2*njp][0], blf[2*njp][1],
                        blf[2*njp+1][0], blf[2*njp+1][1], baddr + BR2);
            }
            uint32_t af[4][4], afl[4][4];
#pragma unroll
            for (int mi = 0; mi < 4; mi++) {
                uint32_t aaddr = abase + (uint32_t)(wm*64 + mi*16 + arow) * ROWB
                               + s*32 + acol;
                ldsm_x4(af[mi][0], af[mi][1], af[mi][2], af[mi][3], aaddr);
                ldsm_x4(afl[mi][0], afl[mi][1], afl[mi][2], afl[mi][3], aaddr + AR2);
            }
#pragma unroll
            for (int mi = 0; mi < 4; mi++)
#pragma unroll
                for (int nj = 0; nj < 4; nj++)
                    mma16816(acc[mi][nj], af[mi], bhf[nj]);   // hi*hi
#pragma unroll
            for (int mi = 0; mi < 4; mi++)
#pragma unroll
                for (int nj = 0; nj < 4; nj++)
                    mma16816(acc[mi][nj], af[mi], blf[nj]);   // hi*lo
#pragma unroll
            for (int mi = 0; mi < 4; mi++)
#pragma unroll
                for (int nj = 0; nj < 4; nj++)
                    mma16816(acc[mi][nj], afl[mi], bhf[nj]);  // lo*hi
        }
        __syncthreads();
    }

#pragma unroll
    for (int mi = 0; mi < 4; mi++) {
#pragma unroll
        for (int nj = 0; nj < 4; nj++) {
            int r0  = m0 + wm*64 + mi*16 + (lane >> 2);
            int col = n0 + wn*32 + nj*8 + (lane & 3) * 2;
            size_t o0 = (size_t)r0 * N + col;
            size_t o1 = (size_t)(r0 + 8) * N + col;
            if (SPLIT) {
                uint32_t h0, l0, h1, l1;
                split2(acc[mi][nj][0]*oscale, acc[mi][nj][1]*oscale, h0, l0);
                split2(acc[mi][nj][2]*oscale, acc[mi][nj][3]*oscale, h1, l1);
                *(uint32_t*)(Ch + o0) = h0;
                *(uint32_t*)(Cl + o0) = l0;
                *(uint32_t*)(Ch + o1) = h1;
                *(uint32_t*)(Cl + o1) = l1;
            } else {
                float2 v01, v23;
                v01.x = acc[mi][nj][0]; v01.y = acc[mi][nj][1];
                v23.x = acc[mi][nj][2]; v23.y = acc[mi][nj][3];
                float2 q0 = *(const float2*)(R + o0);
                float2 q1 = *(const float2*)(R + o1);
                v01.x += q0.x; v01.y += q0.y;
                v23.x += q1.x; v23.y += q1.y;
                *(float2*)(C + o0) = v01;
                *(float2*)(C + o1) = v23;
            }
        }
    }
}

// ---------------------------------------------------------------------------
// mma flash attention. Block: 128 queries x head x batch, 256 threads (8 warps,
// 16 q-rows each), 2 CTA/SM. 32 kv tiles of 64 keys, cp.async double-buffered.
// S = Qh.Kh + Qh.Kl + Ql.Kh ; PV = Ph.Vh + Ph.Vl + Pl.Vh.
// K fragments loaded as x4 (two n-tiles per LDSM). Epilogue writes split AV.
// ---------------------------------------------------------------------------
#define AROW 144
#define QH_OFF 0
#define QL_OFF 18432
#define KVBUF_OFF 36864
#define KVBUF_SZ  36864
#define ATTN_SMEM (KVBUF_OFF + 2*KVBUF_SZ)   // 110592

__global__ __launch_bounds__(256, 2) void attn_mma(
    const ushort_t* __restrict__ Qh, const ushort_t* __restrict__ Ql,
    const ushort_t* __restrict__ KVh, const ushort_t* __restrict__ KVl,
    ushort_t* __restrict__ AVh, ushort_t* __restrict__ AVl)
{
    extern __shared__ __align__(128) char sm[];
    const uint32_t sb = smem_u32(sm);
    const int qt = blockIdx.x, n = blockIdx.y, b = blockIdx.z;
    const int tid = threadIdx.x;
    const int wid = tid >> 5, lane = tid & 31;

    const int l8   = lane & 7;
    const int arow = ((lane >> 3) & 1) * 8 + l8;
    const int acol = ((lane >> 4) & 1) * 16;
    const int b4row = ((lane >> 4) & 1) * 8 + l8;
    const int b4col = ((lane >> 3) & 1) * 16;

    {
        int c0 = tid * 4;
#pragma unroll
        for (int u = 0; u < 4; u++) {
            int cid = c0 + u;
            int row = cid >> 3, c16 = cid & 7;
            size_t grow = (size_t)(qt*128 + row) * BB + b;
            size_t goff = grow * DM + n * DH + c16 * 8;
            cp16(sb + QH_OFF + row*AROW + c16*16, Qh + goff);
            cp16(sb + QL_OFF + row*AROW + c16*16, Ql + goff);
        }
    }
    {
        int c0 = tid * 2;
#pragma unroll
        for (int u = 0; u < 2; u++) {
            int cid = c0 + u;
            int row = cid >> 3, c16 = cid & 7;
            size_t gr = (size_t)(row) * BB + b;
            size_t ko = gr * (2*DM) + n * DH + c16 * 8;
            size_t vo = ko + DM;
            uint32_t so = sb + KVBUF_OFF + row*AROW + c16*16;
            cp16(so,         KVh + ko);
            cp16(so +  9216, KVl + ko);
            cp16(so + 18432, KVh + vo);
            cp16(so + 27648, KVl + vo);
        }
    }
    CP_COMMIT();

    float o[8][4];
#pragma unroll
    for (int dj = 0; dj < 8; dj++)
#pragma unroll
        for (int e = 0; e < 4; e++) o[dj][e] = 0.f;
    float m0 = -1e30f, m1 = -1e30f, lac0 = 0.f, lac1 = 0.f;

    for (int jt = 0; jt < KVL/64; jt++) {
        if (jt + 1 < KVL/64) {
            uint32_t bufn = sb + KVBUF_OFF + (uint32_t)((jt+1) & 1) * KVBUF_SZ;
            int c0 = tid * 2;
#pragma unroll
            for (int u = 0; u < 2; u++) {
                int cid = c0 + u;
                int row = cid >> 3, c16 = cid & 7;
                size_t gr = (size_t)((jt+1)*64 + row) * BB + b;
                size_t ko = gr * (2*DM) + n * DH + c16 * 8;
                size_t vo = ko + DM;
                uint32_t so = bufn + row*AROW + c16*16;
                cp16(so,         KVh + ko);
                cp16(so +  9216, KVl + ko);
                cp16(so + 18432, KVh + vo);
                cp16(so + 27648, KVl + vo);
            }
            CP_COMMIT();
            CP_WAIT1();
        } else {
            CP_WAIT0();
        }
        __syncthreads();

        const uint32_t kb = sb + KVBUF_OFF + (uint32_t)(jt & 1) * KVBUF_SZ;
        const uint32_t vb = kb + 18432;

        float s[8][4];
#pragma unroll
        for (int nj = 0; nj < 8; nj++)
#pragma unroll
            for (int e = 0; e < 4; e++) s[nj][e] = 0.f;

#pragma unroll
        for (int ks = 0; ks < 4; ks++) {
            uint32_t qf[4], qfl[4];
            uint32_t qaddr = sb + QH_OFF + (uint32_t)(wid*16 + arow)*AROW + ks*32 + acol;
            ldsm_x4(qf[0], qf[1], qf[2], qf[3], qaddr);
            ldsm_x4(qfl[0], qfl[1], qfl[2], qfl[3], qaddr + (QL_OFF - QH_OFF));
#pragma unroll
            for (int njp = 0; njp < 4; njp++) {
                uint32_t kh[4], kl[4];
                uint32_t kaddr = kb + (uint32_t)(njp*16 + b4row)*AROW + ks*32 + b4col;
                ldsm_x4(kh[0], kh[1], kh[2], kh[3], kaddr);
                ldsm_x4(kl[0], kl[1], kl[2], kl[3], kaddr + 9216);
                mma16816(s[2*njp],   qf,  kh);
                mma16816(s[2*njp+1], qf,  kh + 2);
                mma16816(s[2*njp],   qf,  kl);
                mma16816(s[2*njp+1], qf,  kl + 2);
                mma16816(s[2*njp],   qfl, kh);
                mma16816(s[2*njp+1], qfl, kh + 2);
            }
        }

        float rmax0 = -1e30f, rmax1 = -1e30f;
#pragma unroll
        for (int nj = 0; nj < 8; nj++) {
            rmax0 = fmaxf(rmax0, fmaxf(s[nj][0], s[nj][1]));
            rmax1 = fmaxf(rmax1, fmaxf(s[nj][2], s[nj][3]));
        }
        rmax0 = fmaxf(rmax0, __shfl_xor_sync(0xffffffffu, rmax0, 1));
        rmax0 = fmaxf(rmax0, __shfl_xor_sync(0xffffffffu, rmax0, 2));
        rmax1 = fmaxf(rmax1, __shfl_xor_sync(0xffffffffu, rmax1, 1));
        rmax1 = fmaxf(rmax1, __shfl_xor_sync(0xffffffffu, rmax1, 2));
        float mn0 = fmaxf(m0, rmax0), mn1 = fmaxf(m1, rmax1);
        float fc0 = __expf(m0 - mn0), fc1 = __expf(m1 - mn1);
        m0 = mn0; m1 = mn1;
        float sum0 = 0.f, sum1 = 0.f;
#pragma unroll
        for (int nj = 0; nj < 8; nj++) {
            float p0 = __expf(s[nj][0] - mn0);
            float p1 = __expf(s[nj][1] - mn0);
            float p2 = __expf(s[nj][2] - mn1);
            float p3 = __expf(s[nj][3] - mn1);
            s[nj][0] = p0; s[nj][1] = p1; s[nj][2] = p2; s[nj][3] = p3;
            sum0 += p0 + p1; sum1 += p2 + p3;
        }
        sum0 += __shfl_xor_sync(0xffffffffu, sum0, 1);
        sum0 += __shfl_xor_sync(0xffffffffu, sum0, 2);
        sum1 += __shfl_xor_sync(0xffffffffu, sum1, 1);
        sum1 += __shfl_xor_sync(0xffffffffu, sum1, 2);
        lac0 = lac0 * fc0 + sum0;
        lac1 = lac1 * fc1 + sum1;
#pragma unroll
        for (int dj = 0; dj < 8; dj++) {
            o[dj][0] *= fc0; o[dj][1] *= fc0;
            o[dj][2] *= fc1; o[dj][3] *= fc1;
        }

#pragma unroll
        for (int ks = 0; ks < 4; ks++) {
            uint32_t ah[4], al[4];
            split2(s[2*ks][0],   s[2*ks][1],   ah[0], al[0]);
            split2(s[2*ks][2],   s[2*ks][3],   ah[1], al[1]);
            split2(s[2*ks+1][0], s[2*ks+1][1], ah[2], al[2]);
            split2(s[2*ks+1][2], s[2*ks+1][3], ah[3], al[3]);
#pragma unroll
            for (int djp = 0; djp < 4; djp++) {
                int dj = djp * 2;
                int mm = lane >> 3;
                uint32_t vaddr = vb
                    + (uint32_t)(ks*16 + (mm & 1)*8 + l8) * AROW
                    + (uint32_t)(dj + (mm >> 1)) * 16;
                uint32_t vh[4], vl[4];
                ldsm_x4t(vh[0], vh[1], vh[2], vh[3], vaddr);
                ldsm_x4t(vl[0], vl[1], vl[2], vl[3], vaddr + 9216);
                mma16816(o[dj],   ah, vh);
                mma16816(o[dj+1], ah, vh + 2);
                mma16816(o[dj],   ah, vl);
                mma16816(o[dj+1], ah, vl + 2);
                mma16816(o[dj],   al, vh);
                mma16816(o[dj+1], al, vh + 2);
            }
        }
        __syncthreads();
    }

    // ---- epilogue: divide by l, split to bf16 hi/lo ----
    float inv0 = 1.f / lac0, inv1 = 1.f / lac1;
    int g = lane >> 2;
    size_t gr0 = ((size_t)(qt*128 + wid*16 + g)) * BB + b;
    size_t gr1 = gr0 + (size_t)8 * BB;
    int colb = n * DH + (lane & 3) * 2;
#pragma unroll
    for (int dj = 0; dj < 8; dj++) {
        uint32_t h0, l0, h1, l1;
        split2(o[dj][0] * inv0, o[dj][1] * inv0, h0, l0);
        split2(o[dj][2] * inv1, o[dj][3] * inv1, h1, l1);
        *(uint32_t*)(AVh + gr0 * DM + colb + dj*8) = h0;
        *(uint32_t*)(AVl + gr0 * DM + colb + dj*8) = l0;
        *(uint32_t*)(AVh + gr1 * DM + colb + dj*8) = h1;
        *(uint32_t*)(AVl + gr1 * DM + colb + dj*8) = l1;
    }
}

// ---------------------------------------------------------------------------
// LayerNorm over rows of 1024.
// ---------------------------------------------------------------------------
__global__ __launch_bounds__(256) void ln_kernel(
    const float* __restrict__ Y, const float* __restrict__ gamma,
    const float* __restrict__ beta, float* __restrict__ out)
{
    __shared__ float red1[8];
    __shared__ float red2[8];
    const int row = blockIdx.x, tid = threadIdx.x;
    const float* y = Y + (size_t)row * DM;
    float v[4];
#pragma unroll
    for (int u = 0; u < 4; u++) v[u] = y[tid + u*256];

    float s = v[0] + v[1] + v[2] + v[3];
#pragma unroll
    for (int m = 16; m; m >>= 1) s += __shfl_xor_sync(0xffffffffu, s, m);
    if ((tid & 31) == 0) red1[tid >> 5] = s;
    __syncthreads();
    float tot = 0.f;
#pragma unroll
    for (int w = 0; w < 8; w++) tot += red1[w];
    float mu = tot * (1.f / DM);

    float q = 0.f;
#pragma unroll
    for (int u = 0; u < 4; u++) { float d = v[u] - mu; q += d * d; }
#pragma unroll
    for (int m = 16; m; m >>= 1) q += __shfl_xor_sync(0xffffffffu, q, m);
    if ((tid & 31) == 0) red2[tid >> 5] = q;
    __syncthreads();
    float qtot = 0.f;
#pragma unroll
    for (int w = 0; w < 8; w++) qtot += red2[w];
    float inv = rsqrtf(qtot * (1.f / DM) + 1e-5f);

#pragma unroll
    for (int u = 0; u < 4; u++) {
        int cix = tid + u*256;
        out[(size_t)row * DM + cix] = (v[u] - mu) * inv * gamma[cix] + beta[cix];
    }
}

// ---------------------------------------------------------------------------
extern "C" void kernel_launch(void* const* d_in, const int* in_sizes, int n_in,
                              void* d_out, int out_size)
{
    const float* h     = (const float*)d_in[0];
    const float* c     = (const float*)d_in[1];
    const float* Wq    = (const float*)d_in[2];
    const float* Wkv   = (const float*)d_in[3];
    const float* Wo    = (const float*)d_in[4];
    const float* gamma = (const float*)d_in[5];
    const float* beta  = (const float*)d_in[6];
    float* out = (float*)d_out;

    ushort_t *hh, *hl, *ch, *cl, *Wqh, *Wql, *Wkvh, *Wkvl, *Woh, *Wol;
    ushort_t *Qh, *Ql, *KVh, *KVl, *AVh, *AVl;
    float *Yb;
    cudaGetSymbolAddress((void**)&hh,   g_hh);
    cudaGetSymbolAddress((void**)&hl,   g_hl);
    cudaGetSymbolAddress((void**)&ch,   g_ch);
    cudaGetSymbolAddress((void**)&cl,   g_cl);
    cudaGetSymbolAddress((void**)&Wqh,  g_Wqh);
    cudaGetSymbolAddress((void**)&Wql,  g_Wql);
    cudaGetSymbolAddress((void**)&Wkvh, g_Wkvh);
    cudaGetSymbolAddress((void**)&Wkvl, g_Wkvl);
    cudaGetSymbolAddress((void**)&Woh,  g_Woh);
    cudaGetSymbolAddress((void**)&Wol,  g_Wol);
    cudaGetSymbolAddress((void**)&Qh,   g_Qh);
    cudaGetSymbolAddress((void**)&Ql,   g_Ql);
    cudaGetSymbolAddress((void**)&KVh,  g_KVh);
    cudaGetSymbolAddress((void**)&KVl,  g_KVl);
    cudaGetSymbolAddress((void**)&AVh,  g_AVh);
    cudaGetSymbolAddress((void**)&AVl,  g_AVl);
    cudaGetSymbolAddress((void**)&Yb,   g_Y);

    cudaFuncSetAttribute(mma_gemm<0>,
                         cudaFuncAttributeMaxDynamicSharedMemorySize, GEMM_SMEM);
    cudaFuncSetAttribute(mma_gemm<1>,
                         cudaFuncAttributeMaxDynamicSharedMemorySize, GEMM_SMEM);
    cudaFuncSetAttribute(attn_mma,
                         cudaFuncAttributeMaxDynamicSharedMemorySize, ATTN_SMEM);

    // ---- pre-split all fp32 inputs into bf16 hi/lo ----
    split_kernel<<<QROWS*DM/1024, 256>>>(h,   hh,   hl,   QROWS*DM);
    split_kernel<<<KVROWS*DM/1024, 256>>>(c,  ch,   cl,   KVROWS*DM);
    split_kernel<<<DM*DM/1024, 256>>>(Wq,     Wqh,  Wql,  DM*DM);
    split_kernel<<<2*DM*DM/1024, 256>>>(Wkv,  Wkvh, Wkvl, 2*DM*DM);
    split_kernel<<<DM*DM/1024, 256>>>(Wo,     Woh,  Wol,  DM*DM);

    // Q = (h @ Wq^T) * ATTN_SCALE -> bf16 hi/lo   [4096 x 1024]
    mma_gemm<1><<<dim3(DM/128, QROWS/256), 512, GEMM_SMEM>>>(
        hh, hl, Wqh, Wql, nullptr, nullptr, Qh, Ql, ATTN_SCALE, QROWS, DM, DM);
    // KV = c @ Wkv^T -> bf16 hi/lo                [8192 x 2048]
    mma_gemm<1><<<dim3(2*DM/128, KVROWS/256), 512, GEMM_SMEM>>>(
        ch, cl, Wkvh, Wkvl, nullptr, nullptr, KVh, KVl, 1.0f, KVROWS, 2*DM, DM);
    // attention -> AV split                       [4096 x 1024]
    attn_mma<<<dim3(QL/128, NH, BB), 256, ATTN_SMEM>>>(Qh, Ql, KVh, KVl, AVh, AVl);
    // Y = AV @ Wo^T + h                           [4096 x 1024]
    mma_gemm<0><<<dim3(DM/128, QROWS/256), 512, GEMM_SMEM>>>(
        AVh, AVl, Woh, Wol, h, Yb, nullptr, nullptr, 1.0f, QROWS, DM, DM);
    // out = LN(Y)
    ln_kernel<<<QROWS, 256>>>(Yb, gamma, beta, out);
}

// round 13
// speedup vs baseline: 1.0745x; 1.0745x over previous
#include <cuda_runtime.h>
#include <cuda_bf16.h>
#include <cstdint>

// ---------------------------------------------------------------------------
// MultiHeadCrossAttn on sm_100 (base target; legacy mma.sync path).
//  Pre-split: ONE fused fp32 -> bf16 hi/lo kernel over h, c, Wq, Wkv, Wo.
//  Q+KV GEMM: ONE fused launch (1280 CTAs) of the R9 128x128 bf16x3 core.
//  O GEMM:    R9 core, fp32 out + residual.
//  Attention: mma flash attention (bf16x3), 2 CTA/SM, x4 K-LDSM (R9).
//  LN:        fp32 two-pass.
// ---------------------------------------------------------------------------

#define NH 16
#define DH 64
#define DM 1024
#define QL 1024
#define KVL 2048
#define BB 4
#define QROWS (QL*BB)     // 4096
#define KVROWS (KVL*BB)   // 8192
#define ATTN_SCALE 0.125f

typedef unsigned short ushort_t;

// pre-split inputs
__device__ ushort_t g_hh [QROWS * DM];
__device__ ushort_t g_hl [QROWS * DM];
__device__ ushort_t g_ch [KVROWS * DM];
__device__ ushort_t g_cl [KVROWS * DM];
__device__ ushort_t g_Wqh [DM * DM];
__device__ ushort_t g_Wql [DM * DM];
__device__ ushort_t g_Wkvh[2 * DM * DM];
__device__ ushort_t g_Wkvl[2 * DM * DM];
__device__ ushort_t g_Woh [DM * DM];
__device__ ushort_t g_Wol [DM * DM];
// intermediates
__device__ ushort_t g_Qh [QROWS * DM];        // prescaled by 0.125
__device__ ushort_t g_Ql [QROWS * DM];
__device__ ushort_t g_KVh[KVROWS * 2 * DM];   // K cols 0-1023, V cols 1024-2047
__device__ ushort_t g_KVl[KVROWS * 2 * DM];
__device__ ushort_t g_AVh[QROWS * DM];
__device__ ushort_t g_AVl[QROWS * DM];
__device__ float    g_Y  [QROWS * DM];

// ------------------------------- helpers -----------------------------------
__device__ __forceinline__ uint32_t smem_u32(const void* p) {
    uint32_t a;
    asm("{ .reg .u64 t; cvta.to.shared.u64 t, %1; cvt.u32.u64 %0, t; }"
        : "=r"(a) : "l"(p));
    return a;
}
__device__ __forceinline__ void ldsm_x4(uint32_t& r0, uint32_t& r1,
                                        uint32_t& r2, uint32_t& r3, uint32_t addr) {
    asm volatile("ldmatrix.sync.aligned.m8n8.x4.shared.b16 {%0,%1,%2,%3}, [%4];"
                 : "=r"(r0), "=r"(r1), "=r"(r2), "=r"(r3) : "r"(addr));
}
__device__ __forceinline__ void ldsm_x4t(uint32_t& r0, uint32_t& r1,
                                         uint32_t& r2, uint32_t& r3, uint32_t addr) {
    asm volatile("ldmatrix.sync.aligned.m8n8.x4.trans.shared.b16 {%0,%1,%2,%3}, [%4];"
                 : "=r"(r0), "=r"(r1), "=r"(r2), "=r"(r3) : "r"(addr));
}
__device__ __forceinline__ void mma16816(float* c, const uint32_t* a, const uint32_t* b) {
    asm volatile("mma.sync.aligned.m16n8k16.row.col.f32.bf16.bf16.f32 "
                 "{%0,%1,%2,%3}, {%4,%5,%6,%7}, {%8,%9}, {%0,%1,%2,%3};"
                 : "+f"(c[0]), "+f"(c[1]), "+f"(c[2]), "+f"(c[3])
                 : "r"(a[0]), "r"(a[1]), "r"(a[2]), "r"(a[3]),
                   "r"(b[0]), "r"(b[1]));
}
__device__ __forceinline__ void split2(float x, float y, uint32_t& hi, uint32_t& lo) {
    __nv_bfloat16 hx = __float2bfloat16_rn(x);
    __nv_bfloat16 hy = __float2bfloat16_rn(y);
    float lxf = x - __bfloat162float(hx);
    float lyf = y - __bfloat162float(hy);
    __nv_bfloat16 lx = __float2bfloat16_rn(lxf);
    __nv_bfloat16 ly = __float2bfloat16_rn(lyf);
    hi = ((uint32_t)__bfloat16_as_ushort(hy) << 16) | __bfloat16_as_ushort(hx);
    lo = ((uint32_t)__bfloat16_as_ushort(ly) << 16) | __bfloat16_as_ushort(lx);
}
__device__ __forceinline__ void cp16(uint32_t saddr, const void* g) {
    asm volatile("cp.async.cg.shared.global [%0], [%1], 16;"
                 :: "r"(saddr), "l"(g));
}
#define CP_COMMIT() asm volatile("cp.async.commit_group;" ::: "memory")
#define CP_WAIT0()  asm volatile("cp.async.wait_group 0;" ::: "memory")
#define CP_WAIT1()  asm volatile("cp.async.wait_group 1;" ::: "memory")

// ---------------------------------------------------------------------------
// Fused split: all five fp32 tensors -> bf16 hi/lo in one launch.
// Segments (element offsets): h[0,4.19M) c[..12.58M) Wq[..13.63M)
// Wkv[..15.73M) Wo[..16.78M). 4 elems/thread.
// ---------------------------------------------------------------------------
#define SEG_H   (QROWS * DM)                 // 4194304
#define SEG_C   (SEG_H + KVROWS * DM)        // 12582912
#define SEG_WQ  (SEG_C + DM * DM)            // 13631488
#define SEG_WKV (SEG_WQ + 2 * DM * DM)       // 15728640
#define SEG_WO  (SEG_WKV + DM * DM)          // 16777216

__global__ __launch_bounds__(256) void split_all(
    const float* __restrict__ h, const float* __restrict__ c,
    const float* __restrict__ Wq, const float* __restrict__ Wkv,
    const float* __restrict__ Wo,
    ushort_t* __restrict__ hh, ushort_t* __restrict__ hl,
    ushort_t* __restrict__ ch, ushort_t* __restrict__ cl,
    ushort_t* __restrict__ Wqh, ushort_t* __restrict__ Wql,
    ushort_t* __restrict__ Wkvh, ushort_t* __restrict__ Wkvl,
    ushort_t* __restrict__ Woh, ushort_t* __restrict__ Wol)
{
    size_t idx = ((size_t)blockIdx.x * 256 + threadIdx.x) * 4;
    if (idx >= SEG_WO) return;
    const float* X; ushort_t *Xh, *Xl; size_t off;
    if      (idx < SEG_H)   { X = h;   Xh = hh;   Xl = hl;   off = 0; }
    else if (idx < SEG_C)   { X = c;   Xh = ch;   Xl = cl;   off = SEG_H; }
    else if (idx < SEG_WQ)  { X = Wq;  Xh = Wqh;  Xl = Wql;  off = SEG_C; }
    else if (idx < SEG_WKV) { X = Wkv; Xh = Wkvh; Xl = Wkvl; off = SEG_WQ; }
    else                    { X = Wo;  Xh = Woh;  Xl = Wol;  off = SEG_WKV; }
    size_t l = idx - off;
    float4 v = *(const float4*)(X + l);
    uint32_t h0, l0, h1, l1;
    split2(v.x, v.y, h0, l0);
    split2(v.z, v.w, h1, l1);
    uint2 hv; hv.x = h0; hv.y = h1;
    uint2 lv; lv.x = l0; lv.y = l1;
    *(uint2*)(Xh + l) = hv;
    *(uint2*)(Xl + l) = lv;
}

// ---------------------------------------------------------------------------
// R9 GEMM core (NT): C = A[M,K] * B[N,K]^T, A/B pre-split hi/lo.
// CTA 128x128, BK=32, 256 threads (8 warps, warp tile 64x32),
// 2-stage cp.async pipeline, dual-live A hi/lo fragments, x4 B-LDSM.
// SPLIT=1: outputs bf16 hi/lo (scaled). SPLIT=0: fp32 + residual.
// ---------------------------------------------------------------------------
#define ROWB  80
#define AREG  10240              // 128 rows * 80B
#define STAGE 40960              // Ah | Al | Bh | Bl
#define GEMM_SMEM (2*STAGE)      // 81920

template<int SPLIT>
__device__ __forceinline__ void gemm_core(
    const ushort_t* __restrict__ Ah_g, const ushort_t* __restrict__ Al_g,
    const ushort_t* __restrict__ Bh_g, const ushort_t* __restrict__ Bl_g,
    const float* __restrict__ R, float* __restrict__ C,
    ushort_t* __restrict__ Ch, ushort_t* __restrict__ Cl,
    float oscale, int N, int K, int m0, int n0, char* sm)
{
    const uint32_t sb = smem_u32(sm);
    const int tid = threadIdx.x;
    const int wid = tid >> 5, lane = tid & 31;
    const int wm = wid & 1, wn = wid >> 1;

    const int cid0 = tid * 2;

    float acc[4][4][4];
#pragma unroll
    for (int mi = 0; mi < 4; mi++)
#pragma unroll
        for (int nj = 0; nj < 4; nj++)
#pragma unroll
            for (int e = 0; e < 4; e++) acc[mi][nj][e] = 0.f;

    const int l8   = lane & 7;
    const int arow = ((lane >> 3) & 1) * 8 + l8;
    const int acol = ((lane >> 4) & 1) * 16;
    const int b4row = ((lane >> 4) & 1) * 8 + l8;
    const int b4col = ((lane >> 3) & 1) * 16;

    const int nchunks = K >> 5;

    auto issue = [&](int kc) {
        const int kk = kc << 5;
        const uint32_t sbase = sb + (uint32_t)(kc & 1) * STAGE;
#pragma unroll
        for (int u = 0; u < 2; u++) {
            int cid = cid0 + u;
            int row = cid >> 2, c16 = cid & 3;
            uint32_t so = sbase + (uint32_t)row * ROWB + c16 * 16;
            size_t ao = (size_t)(m0 + row) * K + kk + c16 * 8;
            size_t bo = (size_t)(n0 + row) * K + kk + c16 * 8;
            cp16(so,          Ah_g + ao);
            cp16(so +   AREG, Al_g + ao);
            cp16(so + 2*AREG, Bh_g + bo);
            cp16(so + 3*AREG, Bl_g + bo);
        }
        CP_COMMIT();
    };

    issue(0);

    for (int kc = 0; kc < nchunks; kc++) {
        if (kc + 1 < nchunks) { issue(kc + 1); CP_WAIT1(); }
        else                  { CP_WAIT0(); }
        __syncthreads();

        const uint32_t abase = sb + (uint32_t)(kc & 1) * STAGE;
        const uint32_t bbase = abase + 2 * AREG;
#pragma unroll
        for (int s = 0; s < 2; s++) {
            uint32_t bhf[4][2], blf[4][2];
#pragma unroll
            for (int njp = 0; njp < 2; njp++) {
                uint32_t baddr = bbase + (uint32_t)(wn*32 + njp*16 + b4row) * ROWB
                               + s*32 + b4col;
                ldsm_x4(bhf[2*njp][0], bhf[2*njp][1],
                        bhf[2*njp+1][0], bhf[2*njp+1][1], baddr);
                ldsm_x4(blf[2*njp][0], blf[2*njp][1],
                        blf[2*njp+1][0], blf[2*njp+1][1], baddr + AREG);
            }
            uint32_t af[4][4], afl[4][4];
#pragma unroll
            for (int mi = 0; mi < 4; mi++) {
                uint32_t aaddr = abase + (uint32_t)(wm*64 + mi*16 + arow) * ROWB
                               + s*32 + acol;
                ldsm_x4(af[mi][0], af[mi][1], af[mi][2], af[mi][3], aaddr);
                ldsm_x4(afl[mi][0], afl[mi][1], afl[mi][2], afl[mi][3], aaddr + AREG);
            }
#pragma unroll
            for (int mi = 0; mi < 4; mi++)
#pragma unroll
                for (int nj = 0; nj < 4; nj++)
                    mma16816(acc[mi][nj], af[mi], bhf[nj]);   // hi*hi
#pragma unroll
            for (int mi = 0; mi < 4; mi++)
#pragma unroll
                for (int nj = 0; nj < 4; nj++)
                    mma16816(acc[mi][nj], af[mi], blf[nj]);   // hi*lo
#pragma unroll
            for (int mi = 0; mi < 4; mi++)
#pragma unroll
                for (int nj = 0; nj < 4; nj++)
                    mma16816(acc[mi][nj], afl[mi], bhf[nj]);  // lo*hi
        }
        __syncthreads();
    }

#pragma unroll
    for (int mi = 0; mi < 4; mi++) {
#pragma unroll
        for (int nj = 0; nj < 4; nj++) {
            int r0  = m0 + wm*64 + mi*16 + (lane >> 2);
            int col = n0 + wn*32 + nj*8 + (lane & 3) * 2;
            size_t o0 = (size_t)r0 * N + col;
            size_t o1 = (size_t)(r0 + 8) * N + col;
            if (SPLIT) {
                uint32_t h0, l0, h1, l1;
                split2(acc[mi][nj][0]*oscale, acc[mi][nj][1]*oscale, h0, l0);
                split2(acc[mi][nj][2]*oscale, acc[mi][nj][3]*oscale, h1, l1);
                *(uint32_t*)(Ch + o0) = h0;
                *(uint32_t*)(Cl + o0) = l0;
                *(uint32_t*)(Ch + o1) = h1;
                *(uint32_t*)(Cl + o1) = l1;
            } else {
                float2 v01, v23;
                v01.x = acc[mi][nj][0]; v01.y = acc[mi][nj][1];
                v23.x = acc[mi][nj][2]; v23.y = acc[mi][nj][3];
                float2 q0 = *(const float2*)(R + o0);
                float2 q1 = *(const float2*)(R + o1);
                v01.x += q0.x; v01.y += q0.y;
                v23.x += q1.x; v23.y += q1.y;
                *(float2*)(C + o0) = v01;
                *(float2*)(C + o1) = v23;
            }
        }
    }
}

// Fused Q+KV projection: 1-D grid of 1280 CTAs. KV tiles [0,1024), Q [1024,1280).
__global__ __launch_bounds__(256, 2) void mma_gemm_qkv(
    const ushort_t* __restrict__ hh, const ushort_t* __restrict__ hl,
    const ushort_t* __restrict__ Wqh, const ushort_t* __restrict__ Wql,
    const ushort_t* __restrict__ ch, const ushort_t* __restrict__ cl,
    const ushort_t* __restrict__ Wkvh, const ushort_t* __restrict__ Wkvl,
    ushort_t* __restrict__ Qh, ushort_t* __restrict__ Ql,
    ushort_t* __restrict__ KVh, ushort_t* __restrict__ KVl)
{
    extern __shared__ __align__(128) char sm[];
    int bid = blockIdx.x;
    if (bid < 1024) {
        int nt = bid & 15, mt = bid >> 4;       // KV: 16 x 64 tiles
        gemm_core<1>(ch, cl, Wkvh, Wkvl, nullptr, nullptr, KVh, KVl,
                     1.0f, 2*DM, DM, mt*128, nt*128, sm);
    } else {
        bid -= 1024;
        int nt = bid & 7, mt = bid >> 3;        // Q: 8 x 32 tiles
        gemm_core<1>(hh, hl, Wqh, Wql, nullptr, nullptr, Qh, Ql,
                     ATTN_SCALE, DM, DM, mt*128, nt*128, sm);
    }
}

// O projection (fp32 out + residual), classic 2-D grid.
__global__ __launch_bounds__(256, 2) void mma_gemm_o(
    const ushort_t* __restrict__ Ah_g, const ushort_t* __restrict__ Al_g,
    const ushort_t* __restrict__ Bh_g, const ushort_t* __restrict__ Bl_g,
    const float* __restrict__ R, float* __restrict__ C)
{
    extern __shared__ __align__(128) char sm[];
    gemm_core<0>(Ah_g, Al_g, Bh_g, Bl_g, R, C, nullptr, nullptr,
                 1.0f, DM, DM, blockIdx.y * 128, blockIdx.x * 128, sm);
}

// ---------------------------------------------------------------------------
// mma flash attention (R9). Block: 128 queries x head x batch, 256 threads,
// 2 CTA/SM. 32 kv tiles of 64 keys, cp.async double-buffered.
// S = Qh.Kh + Qh.Kl + Ql.Kh ; PV = Ph.Vh + Ph.Vl + Pl.Vh.
// ---------------------------------------------------------------------------
#define AROW 144
#define QH_OFF 0
#define QL_OFF 18432
#define KVBUF_OFF 36864
#define KVBUF_SZ  36864
#define ATTN_SMEM (KVBUF_OFF + 2*KVBUF_SZ)   // 110592

__global__ __launch_bounds__(256, 2) void attn_mma(
    const ushort_t* __restrict__ Qh, const ushort_t* __restrict__ Ql,
    const ushort_t* __restrict__ KVh, const ushort_t* __restrict__ KVl,
    ushort_t* __restrict__ AVh, ushort_t* __restrict__ AVl)
{
    extern __shared__ __align__(128) char sm[];
    const uint32_t sb = smem_u32(sm);
    const int qt = blockIdx.x, n = blockIdx.y, b = blockIdx.z;
    const int tid = threadIdx.x;
    const int wid = tid >> 5, lane = tid & 31;

    const int l8   = lane & 7;
    const int arow = ((lane >> 3) & 1) * 8 + l8;
    const int acol = ((lane >> 4) & 1) * 16;
    const int b4row = ((lane >> 4) & 1) * 8 + l8;
    const int b4col = ((lane >> 3) & 1) * 16;

    {
        int c0 = tid * 4;
#pragma unroll
        for (int u = 0; u < 4; u++) {
            int cid = c0 + u;
            int row = cid >> 3, c16 = cid & 7;
            size_t grow = (size_t)(qt*128 + row) * BB + b;
            size_t goff = grow * DM + n * DH + c16 * 8;
            cp16(sb + QH_OFF + row*AROW + c16*16, Qh + goff);
            cp16(sb + QL_OFF + row*AROW + c16*16, Ql + goff);
        }
    }
    {
        int c0 = tid * 2;
#pragma unroll
        for (int u = 0; u < 2; u++) {
            int cid = c0 + u;
            int row = cid >> 3, c16 = cid & 7;
            size_t gr = (size_t)(row) * BB + b;
            size_t ko = gr * (2*DM) + n * DH + c16 * 8;
            size_t vo = ko + DM;
            uint32_t so = sb + KVBUF_OFF + row*AROW + c16*16;
            cp16(so,         KVh + ko);
            cp16(so +  9216, KVl + ko);
            cp16(so + 18432, KVh + vo);
            cp16(so + 27648, KVl + vo);
        }
    }
    CP_COMMIT();

    float o[8][4];
#pragma unroll
    for (int dj = 0; dj < 8; dj++)
#pragma unroll
        for (int e = 0; e < 4; e++) o[dj][e] = 0.f;
    float m0 = -1e30f, m1 = -1e30f, lac0 = 0.f, lac1 = 0.f;

    for (int jt = 0; jt < KVL/64; jt++) {
        if (jt + 1 < KVL/64) {
            uint32_t bufn = sb + KVBUF_OFF + (uint32_t)((jt+1) & 1) * KVBUF_SZ;
            int c0 = tid * 2;
#pragma unroll
            for (int u = 0; u < 2; u++) {
                int cid = c0 + u;
                int row = cid >> 3, c16 = cid & 7;
                size_t gr = (size_t)((jt+1)*64 + row) * BB + b;
                size_t ko = gr * (2*DM) + n * DH + c16 * 8;
                size_t vo = ko + DM;
                uint32_t so = bufn + row*AROW + c16*16;
                cp16(so,         KVh + ko);
                cp16(so +  9216, KVl + ko);
                cp16(so + 18432, KVh + vo);
                cp16(so + 27648, KVl + vo);
            }
            CP_COMMIT();
            CP_WAIT1();
        } else {
            CP_WAIT0();
        }
        __syncthreads();

        const uint32_t kb = sb + KVBUF_OFF + (uint32_t)(jt & 1) * KVBUF_SZ;
        const uint32_t vb = kb + 18432;

        float s[8][4];
#pragma unroll
        for (int nj = 0; nj < 8; nj++)
#pragma unroll
            for (int e = 0; e < 4; e++) s[nj][e] = 0.f;

#pragma unroll
        for (int ks = 0; ks < 4; ks++) {
            uint32_t qf[4], qfl[4];
            uint32_t qaddr = sb + QH_OFF + (uint32_t)(wid*16 + arow)*AROW + ks*32 + acol;
            ldsm_x4(qf[0], qf[1], qf[2], qf[3], qaddr);
            ldsm_x4(qfl[0], qfl[1], qfl[2], qfl[3], qaddr + (QL_OFF - QH_OFF));
#pragma unroll
            for (int njp = 0; njp < 4; njp++) {
                uint32_t kh[4], kl[4];
                uint32_t kaddr = kb + (uint32_t)(njp*16 + b4row)*AROW + ks*32 + b4col;
                ldsm_x4(kh[0], kh[1], kh[2], kh[3], kaddr);
                ldsm_x4(kl[0], kl[1], kl[2], kl[3], kaddr + 9216);
                mma16816(s[2*njp],   qf,  kh);
                mma16816(s[2*njp+1], qf,  kh + 2);
                mma16816(s[2*njp],   qf,  kl);
                mma16816(s[2*njp+1], qf,  kl + 2);
                mma16816(s[2*njp],   qfl, kh);
                mma16816(s[2*njp+1], qfl, kh + 2);
            }
        }

        float rmax0 = -1e30f, rmax1 = -1e30f;
#pragma unroll
        for (int nj = 0; nj < 8; nj++) {
            rmax0 = fmaxf(rmax0, fmaxf(s[nj][0], s[nj][1]));
            rmax1 = fmaxf(rmax1, fmaxf(s[nj][2], s[nj][3]));
        }
        rmax0 = fmaxf(rmax0, __shfl_xor_sync(0xffffffffu, rmax0, 1));
        rmax0 = fmaxf(rmax0, __shfl_xor_sync(0xffffffffu, rmax0, 2));
        rmax1 = fmaxf(rmax1, __shfl_xor_sync(0xffffffffu, rmax1, 1));
        rmax1 = fmaxf(rmax1, __shfl_xor_sync(0xffffffffu, rmax1, 2));
        float mn0 = fmaxf(m0, rmax0), mn1 = fmaxf(m1, rmax1);
        float fc0 = __expf(m0 - mn0), fc1 = __expf(m1 - mn1);
        m0 = mn0; m1 = mn1;
        float sum0 = 0.f, sum1 = 0.f;
#pragma unroll
        for (int nj = 0; nj < 8; nj++) {
            float p0 = __expf(s[nj][0] - mn0);
            float p1 = __expf(s[nj][1] - mn0);
            float p2 = __expf(s[nj][2] - mn1);
            float p3 = __expf(s[nj][3] - mn1);
            s[nj][0] = p0; s[nj][1] = p1; s[nj][2] = p2; s[nj][3] = p3;
            sum0 += p0 + p1; sum1 += p2 + p3;
        }
        sum0 += __shfl_xor_sync(0xffffffffu, sum0, 1);
        sum0 += __shfl_xor_sync(0xffffffffu, sum0, 2);
        sum1 += __shfl_xor_sync(0xffffffffu, sum1, 1);
        sum1 += __shfl_xor_sync(0xffffffffu, sum1, 2);
        lac0 = lac0 * fc0 + sum0;
        lac1 = lac1 * fc1 + sum1;
#pragma unroll
        for (int dj = 0; dj < 8; dj++) {
            o[dj][0] *= fc0; o[dj][1] *= fc0;
            o[dj][2] *= fc1; o[dj][3] *= fc1;
        }

#pragma unroll
        for (int ks = 0; ks < 4; ks++) {
            uint32_t ah[4], al[4];
            split2(s[2*ks][0],   s[2*ks][1],   ah[0], al[0]);
            split2(s[2*ks][2],   s[2*ks][3],   ah[1], al[1]);
            split2(s[2*ks+1][0], s[2*ks+1][1], ah[2], al[2]);
            split2(s[2*ks+1][2], s[2*ks+1][3], ah[3], al[3]);
#pragma unroll
            for (int djp = 0; djp < 4; djp++) {
                int dj = djp * 2;
                int mm = lane >> 3;
                uint32_t vaddr = vb
                    + (uint32_t)(ks*16 + (mm & 1)*8 + l8) * AROW
                    + (uint32_t)(dj + (mm >> 1)) * 16;
                uint32_t vh[4], vl[4];
                ldsm_x4t(vh[0], vh[1], vh[2], vh[3], vaddr);
                ldsm_x4t(vl[0], vl[1], vl[2], vl[3], vaddr + 9216);
                mma16816(o[dj],   ah, vh);
                mma16816(o[dj+1], ah, vh + 2);
                mma16816(o[dj],   ah, vl);
                mma16816(o[dj+1], ah, vl + 2);
                mma16816(o[dj],   al, vh);
                mma16816(o[dj+1], al, vh + 2);
            }
        }
        __syncthreads();
    }

    // ---- epilogue: divide by l, split to bf16 hi/lo ----
    float inv0 = 1.f / lac0, inv1 = 1.f / lac1;
    int g = lane >> 2;
    size_t gr0 = ((size_t)(qt*128 + wid*16 + g)) * BB + b;
    size_t gr1 = gr0 + (size_t)8 * BB;
    int colb = n * DH + (lane & 3) * 2;
#pragma unroll
    for (int dj = 0; dj < 8; dj++) {
        uint32_t h0, l0, h1, l1;
        split2(o[dj][0] * inv0, o[dj][1] * inv0, h0, l0);
        split2(o[dj][2] * inv1, o[dj][3] * inv1, h1, l1);
        *(uint32_t*)(AVh + gr0 * DM + colb + dj*8) = h0;
        *(uint32_t*)(AVl + gr0 * DM + colb + dj*8) = l0;
        *(uint32_t*)(AVh + gr1 * DM + colb + dj*8) = h1;
        *(uint32_t*)(AVl + gr1 * DM + colb + dj*8) = l1;
    }
}

// ---------------------------------------------------------------------------
// LayerNorm over rows of 1024.
// ---------------------------------------------------------------------------
__global__ __launch_bounds__(256) void ln_kernel(
    const float* __restrict__ Y, const float* __restrict__ gamma,
    const float* __restrict__ beta, float* __restrict__ out)
{
    __shared__ float red1[8];
    __shared__ float red2[8];
    const int row = blockIdx.x, tid = threadIdx.x;
    const float* y = Y + (size_t)row * DM;
    float v[4];
#pragma unroll
    for (int u = 0; u < 4; u++) v[u] = y[tid + u*256];

    float s = v[0] + v[1] + v[2] + v[3];
#pragma unroll
    for (int m = 16; m; m >>= 1) s += __shfl_xor_sync(0xffffffffu, s, m);
    if ((tid & 31) == 0) red1[tid >> 5] = s;
    __syncthreads();
    float tot = 0.f;
#pragma unroll
    for (int w = 0; w < 8; w++) tot += red1[w];
    float mu = tot * (1.f / DM);

    float q = 0.f;
#pragma unroll
    for (int u = 0; u < 4; u++) { float d = v[u] - mu; q += d * d; }
#pragma unroll
    for (int m = 16; m; m >>= 1) q += __shfl_xor_sync(0xffffffffu, q, m);
    if ((tid & 31) == 0) red2[tid >> 5] = q;
    __syncthreads();
    float qtot = 0.f;
#pragma unroll
    for (int w = 0; w < 8; w++) qtot += red2[w];
    float inv = rsqrtf(qtot * (1.f / DM) + 1e-5f);

#pragma unroll
    for (int u = 0; u < 4; u++) {
        int cix = tid + u*256;
        out[(size_t)row * DM + cix] = (v[u] - mu) * inv * gamma[cix] + beta[cix];
    }
}

// ---------------------------------------------------------------------------
extern "C" void kernel_launch(void* const* d_in, const int* in_sizes, int n_in,
                              void* d_out, int out_size)
{
    const float* h     = (const float*)d_in[0];
    const float* c     = (const float*)d_in[1];
    const float* Wq    = (const float*)d_in[2];
    const float* Wkv   = (const float*)d_in[3];
    const float* Wo    = (const float*)d_in[4];
    const float* gamma = (const float*)d_in[5];
    const float* beta  = (const float*)d_in[6];
    float* out = (float*)d_out;

    ushort_t *hh, *hl, *ch, *cl, *Wqh, *Wql, *Wkvh, *Wkvl, *Woh, *Wol;
    ushort_t *Qh, *Ql, *KVh, *KVl, *AVh, *AVl;
    float *Yb;
    cudaGetSymbolAddress((void**)&hh,   g_hh);
    cudaGetSymbolAddress((void**)&hl,   g_hl);
    cudaGetSymbolAddress((void**)&ch,   g_ch);
    cudaGetSymbolAddress((void**)&cl,   g_cl);
    cudaGetSymbolAddress((void**)&Wqh,  g_Wqh);
    cudaGetSymbolAddress((void**)&Wql,  g_Wql);
    cudaGetSymbolAddress((void**)&Wkvh, g_Wkvh);
    cudaGetSymbolAddress((void**)&Wkvl, g_Wkvl);
    cudaGetSymbolAddress((void**)&Woh,  g_Woh);
    cudaGetSymbolAddress((void**)&Wol,  g_Wol);
    cudaGetSymbolAddress((void**)&Qh,   g_Qh);
    cudaGetSymbolAddress((void**)&Ql,   g_Ql);
    cudaGetSymbolAddress((void**)&KVh,  g_KVh);
    cudaGetSymbolAddress((void**)&KVl,  g_KVl);
    cudaGetSymbolAddress((void**)&AVh,  g_AVh);
    cudaGetSymbolAddress((void**)&AVl,  g_AVl);
    cudaGetSymbolAddress((void**)&Yb,   g_Y);

    cudaFuncSetAttribute(mma_gemm_qkv,
                         cudaFuncAttributeMaxDynamicSharedMemorySize, GEMM_SMEM);
    cudaFuncSetAttribute(mma_gemm_o,
                         cudaFuncAttributeMaxDynamicSharedMemorySize, GEMM_SMEM);
    cudaFuncSetAttribute(attn_mma,
                         cudaFuncAttributeMaxDynamicSharedMemorySize, ATTN_SMEM);

    // ---- fused pre-split of all fp32 inputs ----
    split_all<<<SEG_WO/1024, 256>>>(h, c, Wq, Wkv, Wo,
                                    hh, hl, ch, cl, Wqh, Wql,
                                    Wkvh, Wkvl, Woh, Wol);

    // ---- fused Q + KV projections (1280 CTAs) ----
    mma_gemm_qkv<<<1280, 256, GEMM_SMEM>>>(hh, hl, Wqh, Wql,
                                           ch, cl, Wkvh, Wkvl,
                                           Qh, Ql, KVh, KVl);

    // attention -> AV split                       [4096 x 1024]
    attn_mma<<<dim3(QL/128, NH, BB), 256, ATTN_SMEM>>>(Qh, Ql, KVh, KVl, AVh, AVl);

    // Y = AV @ Wo^T + h                           [4096 x 1024]
    mma_gemm_o<<<dim3(DM/128, QROWS/128), 256, GEMM_SMEM>>>(
        AVh, AVl, Woh, Wol, h, Yb);

    // out = LN(Y)
    ln_kernel<<<QROWS, 256>>>(Yb, gamma, beta, out);
}

// round 14
// speedup vs baseline: 1.1016x; 1.0252x over previous
#include <cuda_runtime.h>
#include <cuda_bf16.h>
#include <cstdint>

// ---------------------------------------------------------------------------
// MultiHeadCrossAttn on sm_100 (base target; legacy mma.sync path).
//  Pre-split: ONE fused fp32 -> bf16 hi/lo kernel over h, c, Wq, Wkv, Wo.
//  Q+KV GEMM: ONE fused launch (1280 CTAs), 128x128 bf16x3 core,
//             single-barrier cp.async pipeline.
//  O GEMM:    same core, fp32 out + residual.
//  Attention: mma flash attention (bf16x3), 2 CTA/SM, single-barrier pipeline.
//  LN:        fp32 two-pass.
// ---------------------------------------------------------------------------

#define NH 16
#define DH 64
#define DM 1024
#define QL 1024
#define KVL 2048
#define BB 4
#define QROWS (QL*BB)     // 4096
#define KVROWS (KVL*BB)   // 8192
#define ATTN_SCALE 0.125f

typedef unsigned short ushort_t;

// pre-split inputs
__device__ ushort_t g_hh [QROWS * DM];
__device__ ushort_t g_hl [QROWS * DM];
__device__ ushort_t g_ch [KVROWS * DM];
__device__ ushort_t g_cl [KVROWS * DM];
__device__ ushort_t g_Wqh [DM * DM];
__device__ ushort_t g_Wql [DM * DM];
__device__ ushort_t g_Wkvh[2 * DM * DM];
__device__ ushort_t g_Wkvl[2 * DM * DM];
__device__ ushort_t g_Woh [DM * DM];
__device__ ushort_t g_Wol [DM * DM];
// intermediates
__device__ ushort_t g_Qh [QROWS * DM];        // prescaled by 0.125
__device__ ushort_t g_Ql [QROWS * DM];
__device__ ushort_t g_KVh[KVROWS * 2 * DM];   // K cols 0-1023, V cols 1024-2047
__device__ ushort_t g_KVl[KVROWS * 2 * DM];
__device__ ushort_t g_AVh[QROWS * DM];
__device__ ushort_t g_AVl[QROWS * DM];
__device__ float    g_Y  [QROWS * DM];

// ------------------------------- helpers -----------------------------------
__device__ __forceinline__ uint32_t smem_u32(const void* p) {
    uint32_t a;
    asm("{ .reg .u64 t; cvta.to.shared.u64 t, %1; cvt.u32.u64 %0, t; }"
        : "=r"(a) : "l"(p));
    return a;
}
__device__ __forceinline__ void ldsm_x4(uint32_t& r0, uint32_t& r1,
                                        uint32_t& r2, uint32_t& r3, uint32_t addr) {
    asm volatile("ldmatrix.sync.aligned.m8n8.x4.shared.b16 {%0,%1,%2,%3}, [%4];"
                 : "=r"(r0), "=r"(r1), "=r"(r2), "=r"(r3) : "r"(addr));
}
__device__ __forceinline__ void ldsm_x4t(uint32_t& r0, uint32_t& r1,
                                         uint32_t& r2, uint32_t& r3, uint32_t addr) {
    asm volatile("ldmatrix.sync.aligned.m8n8.x4.trans.shared.b16 {%0,%1,%2,%3}, [%4];"
                 : "=r"(r0), "=r"(r1), "=r"(r2), "=r"(r3) : "r"(addr));
}
__device__ __forceinline__ void mma16816(float* c, const uint32_t* a, const uint32_t* b) {
    asm volatile("mma.sync.aligned.m16n8k16.row.col.f32.bf16.bf16.f32 "
                 "{%0,%1,%2,%3}, {%4,%5,%6,%7}, {%8,%9}, {%0,%1,%2,%3};"
                 : "+f"(c[0]), "+f"(c[1]), "+f"(c[2]), "+f"(c[3])
                 : "r"(a[0]), "r"(a[1]), "r"(a[2]), "r"(a[3]),
                   "r"(b[0]), "r"(b[1]));
}
__device__ __forceinline__ void split2(float x, float y, uint32_t& hi, uint32_t& lo) {
    __nv_bfloat16 hx = __float2bfloat16_rn(x);
    __nv_bfloat16 hy = __float2bfloat16_rn(y);
    float lxf = x - __bfloat162float(hx);
    float lyf = y - __bfloat162float(hy);
    __nv_bfloat16 lx = __float2bfloat16_rn(lxf);
    __nv_bfloat16 ly = __float2bfloat16_rn(lyf);
    hi = ((uint32_t)__bfloat16_as_ushort(hy) << 16) | __bfloat16_as_ushort(hx);
    lo = ((uint32_t)__bfloat16_as_ushort(ly) << 16) | __bfloat16_as_ushort(lx);
}
__device__ __forceinline__ void cp16(uint32_t saddr, const void* g) {
    asm volatile("cp.async.cg.shared.global [%0], [%1], 16;"
                 :: "r"(saddr), "l"(g));
}
#define CP_COMMIT() asm volatile("cp.async.commit_group;" ::: "memory")
#define CP_WAIT0()  asm volatile("cp.async.wait_group 0;" ::: "memory")

// ---------------------------------------------------------------------------
// Fused split: all five fp32 tensors -> bf16 hi/lo in one launch.
// ---------------------------------------------------------------------------
#define SEG_H   (QROWS * DM)                 // 4194304
#define SEG_C   (SEG_H + KVROWS * DM)        // 12582912
#define SEG_WQ  (SEG_C + DM * DM)            // 13631488
#define SEG_WKV (SEG_WQ + 2 * DM * DM)       // 15728640
#define SEG_WO  (SEG_WKV + DM * DM)          // 16777216

__global__ __launch_bounds__(256) void split_all(
    const float* __restrict__ h, const float* __restrict__ c,
    const float* __restrict__ Wq, const float* __restrict__ Wkv,
    const float* __restrict__ Wo,
    ushort_t* __restrict__ hh, ushort_t* __restrict__ hl,
    ushort_t* __restrict__ ch, ushort_t* __restrict__ cl,
    ushort_t* __restrict__ Wqh, ushort_t* __restrict__ Wql,
    ushort_t* __restrict__ Wkvh, ushort_t* __restrict__ Wkvl,
    ushort_t* __restrict__ Woh, ushort_t* __restrict__ Wol)
{
    size_t idx = ((size_t)blockIdx.x * 256 + threadIdx.x) * 4;
    if (idx >= SEG_WO) return;
    const float* X; ushort_t *Xh, *Xl; size_t off;
    if      (idx < SEG_H)   { X = h;   Xh = hh;   Xl = hl;   off = 0; }
    else if (idx < SEG_C)   { X = c;   Xh = ch;   Xl = cl;   off = SEG_H; }
    else if (idx < SEG_WQ)  { X = Wq;  Xh = Wqh;  Xl = Wql;  off = SEG_C; }
    else if (idx < SEG_WKV) { X = Wkv; Xh = Wkvh; Xl = Wkvl; off = SEG_WQ; }
    else                    { X = Wo;  Xh = Woh;  Xl = Wol;  off = SEG_WKV; }
    size_t l = idx - off;
    float4 v = *(const float4*)(X + l);
    uint32_t h0, l0, h1, l1;
    split2(v.x, v.y, h0, l0);
    split2(v.z, v.w, h1, l1);
    uint2 hv; hv.x = h0; hv.y = h1;
    uint2 lv; lv.x = l0; lv.y = l1;
    *(uint2*)(Xh + l) = hv;
    *(uint2*)(Xl + l) = lv;
}

// ---------------------------------------------------------------------------
// GEMM core (NT): C = A[M,K] * B[N,K]^T, A/B pre-split hi/lo.
// CTA 128x128, BK=32, 256 threads (8 warps, warp tile 64x32),
// single-barrier 2-stage cp.async pipeline:
//   wait(all) -> sync -> issue(next) -> compute.
// SPLIT=1: outputs bf16 hi/lo (scaled). SPLIT=0: fp32 + residual.
// ---------------------------------------------------------------------------
#define ROWB  80
#define AREG  10240              // 128 rows * 80B
#define STAGE 40960              // Ah | Al | Bh | Bl
#define GEMM_SMEM (2*STAGE)      // 81920

template<int SPLIT>
__device__ __forceinline__ void gemm_core(
    const ushort_t* __restrict__ Ah_g, const ushort_t* __restrict__ Al_g,
    const ushort_t* __restrict__ Bh_g, const ushort_t* __restrict__ Bl_g,
    const float* __restrict__ R, float* __restrict__ C,
    ushort_t* __restrict__ Ch, ushort_t* __restrict__ Cl,
    float oscale, int N, int K, int m0, int n0, char* sm)
{
    const uint32_t sb = smem_u32(sm);
    const int tid = threadIdx.x;
    const int wid = tid >> 5, lane = tid & 31;
    const int wm = wid & 1, wn = wid >> 1;

    const int cid0 = tid * 2;

    float acc[4][4][4];
#pragma unroll
    for (int mi = 0; mi < 4; mi++)
#pragma unroll
        for (int nj = 0; nj < 4; nj++)
#pragma unroll
            for (int e = 0; e < 4; e++) acc[mi][nj][e] = 0.f;

    const int l8   = lane & 7;
    const int arow = ((lane >> 3) & 1) * 8 + l8;
    const int acol = ((lane >> 4) & 1) * 16;
    const int b4row = ((lane >> 4) & 1) * 8 + l8;
    const int b4col = ((lane >> 3) & 1) * 16;

    const int nchunks = K >> 5;

    auto issue = [&](int kc) {
        const int kk = kc << 5;
        const uint32_t sbase = sb + (uint32_t)(kc & 1) * STAGE;
#pragma unroll
        for (int u = 0; u < 2; u++) {
            int cid = cid0 + u;
            int row = cid >> 2, c16 = cid & 3;
            uint32_t so = sbase + (uint32_t)row * ROWB + c16 * 16;
            size_t ao = (size_t)(m0 + row) * K + kk + c16 * 8;
            size_t bo = (size_t)(n0 + row) * K + kk + c16 * 8;
            cp16(so,          Ah_g + ao);
            cp16(so +   AREG, Al_g + ao);
            cp16(so + 2*AREG, Bh_g + bo);
            cp16(so + 3*AREG, Bl_g + bo);
        }
        CP_COMMIT();
    };

    issue(0);

    for (int kc = 0; kc < nchunks; kc++) {
        CP_WAIT0();                       // stage kc landed (only group in flight)
        __syncthreads();                  // all threads done reading stage kc-1's buddy
        if (kc + 1 < nchunks) issue(kc + 1);   // safe: last reader of that buffer fenced above

        const uint32_t abase = sb + (uint32_t)(kc & 1) * STAGE;
        const uint32_t bbase = abase + 2 * AREG;
#pragma unroll
        for (int s = 0; s < 2; s++) {
            uint32_t bhf[4][2], blf[4][2];
#pragma unroll
            for (int njp = 0; njp < 2; njp++) {
                uint32_t baddr = bbase + (uint32_t)(wn*32 + njp*16 + b4row) * ROWB
                               + s*32 + b4col;
                ldsm_x4(bhf[2*njp][0], bhf[2*njp][1],
                        bhf[2*njp+1][0], bhf[2*njp+1][1], baddr);
                ldsm_x4(blf[2*njp][0], blf[2*njp][1],
                        blf[2*njp+1][0], blf[2*njp+1][1], baddr + AREG);
            }
            uint32_t af[4][4], afl[4][4];
#pragma unroll
            for (int mi = 0; mi < 4; mi++) {
                uint32_t aaddr = abase + (uint32_t)(wm*64 + mi*16 + arow) * ROWB
                               + s*32 + acol;
                ldsm_x4(af[mi][0], af[mi][1], af[mi][2], af[mi][3], aaddr);
                ldsm_x4(afl[mi][0], afl[mi][1], afl[mi][2], afl[mi][3], aaddr + AREG);
            }
#pragma unroll
            for (int mi = 0; mi < 4; mi++)
#pragma unroll
                for (int nj = 0; nj < 4; nj++)
                    mma16816(acc[mi][nj], af[mi], bhf[nj]);   // hi*hi
#pragma unroll
            for (int mi = 0; mi < 4; mi++)
#pragma unroll
                for (int nj = 0; nj < 4; nj++)
                    mma16816(acc[mi][nj], af[mi], blf[nj]);   // hi*lo
#pragma unroll
            for (int mi = 0; mi < 4; mi++)
#pragma unroll
                for (int nj = 0; nj < 4; nj++)
                    mma16816(acc[mi][nj], afl[mi], bhf[nj]);  // lo*hi
        }
    }

#pragma unroll
    for (int mi = 0; mi < 4; mi++) {
#pragma unroll
        for (int nj = 0; nj < 4; nj++) {
            int r0  = m0 + wm*64 + mi*16 + (lane >> 2);
            int col = n0 + wn*32 + nj*8 + (lane & 3) * 2;
            size_t o0 = (size_t)r0 * N + col;
            size_t o1 = (size_t)(r0 + 8) * N + col;
            if (SPLIT) {
                uint32_t h0, l0, h1, l1;
                split2(acc[mi][nj][0]*oscale, acc[mi][nj][1]*oscale, h0, l0);
                split2(acc[mi][nj][2]*oscale, acc[mi][nj][3]*oscale, h1, l1);
                *(uint32_t*)(Ch + o0) = h0;
                *(uint32_t*)(Cl + o0) = l0;
                *(uint32_t*)(Ch + o1) = h1;
                *(uint32_t*)(Cl + o1) = l1;
            } else {
                float2 v01, v23;
                v01.x = acc[mi][nj][0]; v01.y = acc[mi][nj][1];
                v23.x = acc[mi][nj][2]; v23.y = acc[mi][nj][3];
                float2 q0 = *(const float2*)(R + o0);
                float2 q1 = *(const float2*)(R + o1);
                v01.x += q0.x; v01.y += q0.y;
                v23.x += q1.x; v23.y += q1.y;
                *(float2*)(C + o0) = v01;
                *(float2*)(C + o1) = v23;
            }
        }
    }
}

// Fused Q+KV projection: 1-D grid of 1280 CTAs. KV tiles [0,1024), Q [1024,1280).
__global__ __launch_bounds__(256, 2) void mma_gemm_qkv(
    const ushort_t* __restrict__ hh, const ushort_t* __restrict__ hl,
    const ushort_t* __restrict__ Wqh, const ushort_t* __restrict__ Wql,
    const ushort_t* __restrict__ ch, const ushort_t* __restrict__ cl,
    const ushort_t* __restrict__ Wkvh, const ushort_t* __restrict__ Wkvl,
    ushort_t* __restrict__ Qh, ushort_t* __restrict__ Ql,
    ushort_t* __restrict__ KVh, ushort_t* __restrict__ KVl)
{
    extern __shared__ __align__(128) char sm[];
    int bid = blockIdx.x;
    if (bid < 1024) {
        int nt = bid & 15, mt = bid >> 4;       // KV: 16 x 64 tiles
        gemm_core<1>(ch, cl, Wkvh, Wkvl, nullptr, nullptr, KVh, KVl,
                     1.0f, 2*DM, DM, mt*128, nt*128, sm);
    } else {
        bid -= 1024;
        int nt = bid & 7, mt = bid >> 3;        // Q: 8 x 32 tiles
        gemm_core<1>(hh, hl, Wqh, Wql, nullptr, nullptr, Qh, Ql,
                     ATTN_SCALE, DM, DM, mt*128, nt*128, sm);
    }
}

// O projection (fp32 out + residual), classic 2-D grid.
__global__ __launch_bounds__(256, 2) void mma_gemm_o(
    const ushort_t* __restrict__ Ah_g, const ushort_t* __restrict__ Al_g,
    const ushort_t* __restrict__ Bh_g, const ushort_t* __restrict__ Bl_g,
    const float* __restrict__ R, float* __restrict__ C)
{
    extern __shared__ __align__(128) char sm[];
    gemm_core<0>(Ah_g, Al_g, Bh_g, Bl_g, R, C, nullptr, nullptr,
                 1.0f, DM, DM, blockIdx.y * 128, blockIdx.x * 128, sm);
}

// ---------------------------------------------------------------------------
// mma flash attention. Block: 128 queries x head x batch, 256 threads,
// 2 CTA/SM. 32 kv tiles of 64 keys, single-barrier cp.async pipeline.
// S = Qh.Kh + Qh.Kl + Ql.Kh ; PV = Ph.Vh + Ph.Vl + Pl.Vh.
// ---------------------------------------------------------------------------
#define AROW 144
#define QH_OFF 0
#define QL_OFF 18432
#define KVBUF_OFF 36864
#define KVBUF_SZ  36864
#define ATTN_SMEM (KVBUF_OFF + 2*KVBUF_SZ)   // 110592

__global__ __launch_bounds__(256, 2) void attn_mma(
    const ushort_t* __restrict__ Qh, const ushort_t* __restrict__ Ql,
    const ushort_t* __restrict__ KVh, const ushort_t* __restrict__ KVl,
    ushort_t* __restrict__ AVh, ushort_t* __restrict__ AVl)
{
    extern __shared__ __align__(128) char sm[];
    const uint32_t sb = smem_u32(sm);
    const int qt = blockIdx.x, n = blockIdx.y, b = blockIdx.z;
    const int tid = threadIdx.x;
    const int wid = tid >> 5, lane = tid & 31;

    const int l8   = lane & 7;
    const int arow = ((lane >> 3) & 1) * 8 + l8;
    const int acol = ((lane >> 4) & 1) * 16;
    const int b4row = ((lane >> 4) & 1) * 8 + l8;
    const int b4col = ((lane >> 3) & 1) * 16;

    // issue KV tile jt into its double buffer
    auto issue_kv = [&](int jt) {
        uint32_t bufn = sb + KVBUF_OFF + (uint32_t)(jt & 1) * KVBUF_SZ;
        int c0 = tid * 2;
#pragma unroll
        for (int u = 0; u < 2; u++) {
            int cid = c0 + u;
            int row = cid >> 3, c16 = cid & 7;
            size_t gr = (size_t)(jt*64 + row) * BB + b;
            size_t ko = gr * (2*DM) + n * DH + c16 * 8;
            size_t vo = ko + DM;
            uint32_t so = bufn + row*AROW + c16*16;
            cp16(so,         KVh + ko);
            cp16(so +  9216, KVl + ko);
            cp16(so + 18432, KVh + vo);
            cp16(so + 27648, KVl + vo);
        }
        CP_COMMIT();
    };

    // prologue: Q tile + KV tile 0, one commit group
    {
        int c0 = tid * 4;
#pragma unroll
        for (int u = 0; u < 4; u++) {
            int cid = c0 + u;
            int row = cid >> 3, c16 = cid & 7;
            size_t grow = (size_t)(qt*128 + row) * BB + b;
            size_t goff = grow * DM + n * DH + c16 * 8;
            cp16(sb + QH_OFF + row*AROW + c16*16, Qh + goff);
            cp16(sb + QL_OFF + row*AROW + c16*16, Ql + goff);
        }
    }
    issue_kv(0);

    float o[8][4];
#pragma unroll
    for (int dj = 0; dj < 8; dj++)
#pragma unroll
        for (int e = 0; e < 4; e++) o[dj][e] = 0.f;
    float m0 = -1e30f, m1 = -1e30f, lac0 = 0.f, lac1 = 0.f;

    for (int jt = 0; jt < KVL/64; jt++) {
        CP_WAIT0();                          // stage jt (and Q on jt=0) landed
        __syncthreads();                     // prior iter's reads of buddy buffer done
        if (jt + 1 < KVL/64) issue_kv(jt + 1);

        const uint32_t kb = sb + KVBUF_OFF + (uint32_t)(jt & 1) * KVBUF_SZ;
        const uint32_t vb = kb + 18432;

        float s[8][4];
#pragma unroll
        for (int nj = 0; nj < 8; nj++)
#pragma unroll
            for (int e = 0; e < 4; e++) s[nj][e] = 0.f;

#pragma unroll
        for (int ks = 0; ks < 4; ks++) {
            uint32_t qf[4], qfl[4];
            uint32_t qaddr = sb + QH_OFF + (uint32_t)(wid*16 + arow)*AROW + ks*32 + acol;
            ldsm_x4(qf[0], qf[1], qf[2], qf[3], qaddr);
            ldsm_x4(qfl[0], qfl[1], qfl[2], qfl[3], qaddr + (QL_OFF - QH_OFF));
#pragma unroll
            for (int njp = 0; njp < 4; njp++) {
                uint32_t kh[4], kl[4];
                uint32_t kaddr = kb + (uint32_t)(njp*16 + b4row)*AROW + ks*32 + b4col;
                ldsm_x4(kh[0], kh[1], kh[2], kh[3], kaddr);
                ldsm_x4(kl[0], kl[1], kl[2], kl[3], kaddr + 9216);
                mma16816(s[2*njp],   qf,  kh);
                mma16816(s[2*njp+1], qf,  kh + 2);
                mma16816(s[2*njp],   qf,  kl);
                mma16816(s[2*njp+1], qf,  kl + 2);
                mma16816(s[2*njp],   qfl, kh);
                mma16816(s[2*njp+1], qfl, kh + 2);
            }
        }

        float rmax0 = -1e30f, rmax1 = -1e30f;
#pragma unroll
        for (int nj = 0; nj < 8; nj++) {
            rmax0 = fmaxf(rmax0, fmaxf(s[nj][0], s[nj][1]));
            rmax1 = fmaxf(rmax1, fmaxf(s[nj][2], s[nj][3]));
        }
        rmax0 = fmaxf(rmax0, __shfl_xor_sync(0xffffffffu, rmax0, 1));
        rmax0 = fmaxf(rmax0, __shfl_xor_sync(0xffffffffu, rmax0, 2));
        rmax1 = fmaxf(rmax1, __shfl_xor_sync(0xffffffffu, rmax1, 1));
        rmax1 = fmaxf(rmax1, __shfl_xor_sync(0xffffffffu, rmax1, 2));
        float mn0 = fmaxf(m0, rmax0), mn1 = fmaxf(m1, rmax1);
        float fc0 = __expf(m0 - mn0), fc1 = __expf(m1 - mn1);
        m0 = mn0; m1 = mn1;
        float sum0 = 0.f, sum1 = 0.f;
#pragma unroll
        for (int nj = 0; nj < 8; nj++) {
            float p0 = __expf(s[nj][0] - mn0);
            float p1 = __expf(s[nj][1] - mn0);
            float p2 = __expf(s[nj][2] - mn1);
            float p3 = __expf(s[nj][3] - mn1);
            s[nj][0] = p0; s[nj][1] = p1; s[nj][2] = p2; s[nj][3] = p3;
            sum0 += p0 + p1; sum1 += p2 + p3;
        }
        sum0 += __shfl_xor_sync(0xffffffffu, sum0, 1);
        sum0 += __shfl_xor_sync(0xffffffffu, sum0, 2);
        sum1 += __shfl_xor_sync(0xffffffffu, sum1, 1);
        sum1 += __shfl_xor_sync(0xffffffffu, sum1, 2);
        lac0 = lac0 * fc0 + sum0;
        lac1 = lac1 * fc1 + sum1;
#pragma unroll
        for (int dj = 0; dj < 8; dj++) {
            o[dj][0] *= fc0; o[dj][1] *= fc0;
            o[dj][2] *= fc1; o[dj][3] *= fc1;
        }

#pragma unroll
        for (int ks = 0; ks < 4; ks++) {
            uint32_t ah[4], al[4];
            split2(s[2*ks][0],   s[2*ks][1],   ah[0], al[0]);
            split2(s[2*ks][2],   s[2*ks][3],   ah[1], al[1]);
            split2(s[2*ks+1][0], s[2*ks+1][1], ah[2], al[2]);
            split2(s[2*ks+1][2], s[2*ks+1][3], ah[3], al[3]);
#pragma unroll
            for (int djp = 0; djp < 4; djp++) {
                int dj = djp * 2;
                int mm = lane >> 3;
                uint32_t vaddr = vb
                    + (uint32_t)(ks*16 + (mm & 1)*8 + l8) * AROW
                    + (uint32_t)(dj + (mm >> 1)) * 16;
                uint32_t vh[4], vl[4];
                ldsm_x4t(vh[0], vh[1], vh[2], vh[3], vaddr);
                ldsm_x4t(vl[0], vl[1], vl[2], vl[3], vaddr + 9216);
                mma16816(o[dj],   ah, vh);
                mma16816(o[dj+1], ah, vh + 2);
                mma16816(o[dj],   ah, vl);
                mma16816(o[dj+1], ah, vl + 2);
                mma16816(o[dj],   al, vh);
                mma16816(o[dj+1], al, vh + 2);
            }
        }
    }

    // ---- epilogue: divide by l, split to bf16 hi/lo ----
    float inv0 = 1.f / lac0, inv1 = 1.f / lac1;
    int g = lane >> 2;
    size_t gr0 = ((size_t)(qt*128 + wid*16 + g)) * BB + b;
    size_t gr1 = gr0 + (size_t)8 * BB;
    int colb = n * DH + (lane & 3) * 2;
#pragma unroll
    for (int dj = 0; dj < 8; dj++) {
        uint32_t h0, l0, h1, l1;
        split2(o[dj][0] * inv0, o[dj][1] * inv0, h0, l0);
        split2(o[dj][2] * inv1, o[dj][3] * inv1, h1, l1);
        *(uint32_t*)(AVh + gr0 * DM + colb + dj*8) = h0;
        *(uint32_t*)(AVl + gr0 * DM + colb + dj*8) = l0;
        *(uint32_t*)(AVh + gr1 * DM + colb + dj*8) = h1;
        *(uint32_t*)(AVl + gr1 * DM + colb + dj*8) = l1;
    }
}

// ---------------------------------------------------------------------------
// LayerNorm over rows of 1024.
// ---------------------------------------------------------------------------
__global__ __launch_bounds__(256) void ln_kernel(
    const float* __restrict__ Y, const float* __restrict__ gamma,
    const float* __restrict__ beta, float* __restrict__ out)
{
    __shared__ float red1[8];
    __shared__ float red2[8];
    const int row = blockIdx.x, tid = threadIdx.x;
    const float* y = Y + (size_t)row * DM;
    float v[4];
#pragma unroll
    for (int u = 0; u < 4; u++) v[u] = y[tid + u*256];

    float s = v[0] + v[1] + v[2] + v[3];
#pragma unroll
    for (int m = 16; m; m >>= 1) s += __shfl_xor_sync(0xffffffffu, s, m);
    if ((tid & 31) == 0) red1[tid >> 5] = s;
    __syncthreads();
    float tot = 0.f;
#pragma unroll
    for (int w = 0; w < 8; w++) tot += red1[w];
    float mu = tot * (1.f / DM);

    float q = 0.f;
#pragma unroll
    for (int u = 0; u < 4; u++) { float d = v[u] - mu; q += d * d; }
#pragma unroll
    for (int m = 16; m; m >>= 1) q += __shfl_xor_sync(0xffffffffu, q, m);
    if ((tid & 31) == 0) red2[tid >> 5] = q;
    __syncthreads();
    float qtot = 0.f;
#pragma unroll
    for (int w = 0; w < 8; w++) qtot += red2[w];
    float inv = rsqrtf(qtot * (1.f / DM) + 1e-5f);

#pragma unroll
    for (int u = 0; u < 4; u++) {
        int cix = tid + u*256;
        out[(size_t)row * DM + cix] = (v[u] - mu) * inv * gamma[cix] + beta[cix];
    }
}

// ---------------------------------------------------------------------------
extern "C" void kernel_launch(void* const* d_in, const int* in_sizes, int n_in,
                              void* d_out, int out_size)
{
    const float* h     = (const float*)d_in[0];
    const float* c     = (const float*)d_in[1];
    const float* Wq    = (const float*)d_in[2];
    const float* Wkv   = (const float*)d_in[3];
    const float* Wo    = (const float*)d_in[4];
    const float* gamma = (const float*)d_in[5];
    const float* beta  = (const float*)d_in[6];
    float* out = (float*)d_out;

    ushort_t *hh, *hl, *ch, *cl, *Wqh, *Wql, *Wkvh, *Wkvl, *Woh, *Wol;
    ushort_t *Qh, *Ql, *KVh, *KVl, *AVh, *AVl;
    float *Yb;
    cudaGetSymbolAddress((void**)&hh,   g_hh);
    cudaGetSymbolAddress((void**)&hl,   g_hl);
    cudaGetSymbolAddress((void**)&ch,   g_ch);
    cudaGetSymbolAddress((void**)&cl,   g_cl);
    cudaGetSymbolAddress((void**)&Wqh,  g_Wqh);
    cudaGetSymbolAddress((void**)&Wql,  g_Wql);
    cudaGetSymbolAddress((void**)&Wkvh, g_Wkvh);
    cudaGetSymbolAddress((void**)&Wkvl, g_Wkvl);
    cudaGetSymbolAddress((void**)&Woh,  g_Woh);
    cudaGetSymbolAddress((void**)&Wol,  g_Wol);
    cudaGetSymbolAddress((void**)&Qh,   g_Qh);
    cudaGetSymbolAddress((void**)&Ql,   g_Ql);
    cudaGetSymbolAddress((void**)&KVh,  g_KVh);
    cudaGetSymbolAddress((void**)&KVl,  g_KVl);
    cudaGetSymbolAddress((void**)&AVh,  g_AVh);
    cudaGetSymbolAddress((void**)&AVl,  g_AVl);
    cudaGetSymbolAddress((void**)&Yb,   g_Y);

    cudaFuncSetAttribute(mma_gemm_qkv,
                         cudaFuncAttributeMaxDynamicSharedMemorySize, GEMM_SMEM);
    cudaFuncSetAttribute(mma_gemm_o,
                         cudaFuncAttributeMaxDynamicSharedMemorySize, GEMM_SMEM);
    cudaFuncSetAttribute(attn_mma,
                         cudaFuncAttributeMaxDynamicSharedMemorySize, ATTN_SMEM);

    // ---- fused pre-split of all fp32 inputs ----
    split_all<<<SEG_WO/1024, 256>>>(h, c, Wq, Wkv, Wo,
                                    hh, hl, ch, cl, Wqh, Wql,
                                    Wkvh, Wkvl, Woh, Wol);

    // ---- fused Q + KV projections (1280 CTAs) ----
    mma_gemm_qkv<<<1280, 256, GEMM_SMEM>>>(hh, hl, Wqh, Wql,
                                           ch, cl, Wkvh, Wkvl,
                                           Qh, Ql, KVh, KVl);

    // attention -> AV split                       [4096 x 1024]
    attn_mma<<<dim3(QL/128, NH, BB), 256, ATTN_SMEM>>>(Qh, Ql, KVh, KVl, AVh, AVl);

    // Y = AV @ Wo^T + h                           [4096 x 1024]
    mma_gemm_o<<<dim3(DM/128, QROWS/128), 256, GEMM_SMEM>>>(
        AVh, AVl, Woh, Wol, h, Yb);

    // out = LN(Y)
    ln_kernel<<<QROWS, 256>>>(Yb, gamma, beta, out);
}

// round 15
// speedup vs baseline: 1.1325x; 1.0280x over previous
#include <cuda_runtime.h>
#include <cuda_bf16.h>
#include <cstdint>

// ---------------------------------------------------------------------------
// MultiHeadCrossAttn on sm_100 (base target; legacy mma.sync path).
//  Pre-split: ONE fused fp32 -> bf16 hi/lo kernel over h, c, Wq, Wkv, Wo.
//  Q+KV GEMM: ONE fused launch (1280 CTAs), 128x128 bf16x3 core,
//             single-barrier cp.async pipeline, .ca A loads.
//  O GEMM:    same core, fp32 out + residual.
//  Attention: mma flash attention (bf16x3), 256-query CTA (512 thr, 16 warps),
//             single-barrier pipeline -> halved KV L2 traffic.
//  LN:        fp32 two-pass.
// ---------------------------------------------------------------------------

#define NH 16
#define DH 64
#define DM 1024
#define QL 1024
#define KVL 2048
#define BB 4
#define QROWS (QL*BB)     // 4096
#define KVROWS (KVL*BB)   // 8192
#define ATTN_SCALE 0.125f

typedef unsigned short ushort_t;

// pre-split inputs
__device__ ushort_t g_hh [QROWS * DM];
__device__ ushort_t g_hl [QROWS * DM];
__device__ ushort_t g_ch [KVROWS * DM];
__device__ ushort_t g_cl [KVROWS * DM];
__device__ ushort_t g_Wqh [DM * DM];
__device__ ushort_t g_Wql [DM * DM];
__device__ ushort_t g_Wkvh[2 * DM * DM];
__device__ ushort_t g_Wkvl[2 * DM * DM];
__device__ ushort_t g_Woh [DM * DM];
__device__ ushort_t g_Wol [DM * DM];
// intermediates
__device__ ushort_t g_Qh [QROWS * DM];        // prescaled by 0.125
__device__ ushort_t g_Ql [QROWS * DM];
__device__ ushort_t g_KVh[KVROWS * 2 * DM];   // K cols 0-1023, V cols 1024-2047
__device__ ushort_t g_KVl[KVROWS * 2 * DM];
__device__ ushort_t g_AVh[QROWS * DM];
__device__ ushort_t g_AVl[QROWS * DM];
__device__ float    g_Y  [QROWS * DM];

// ------------------------------- helpers -----------------------------------
__device__ __forceinline__ uint32_t smem_u32(const void* p) {
    uint32_t a;
    asm("{ .reg .u64 t; cvta.to.shared.u64 t, %1; cvt.u32.u64 %0, t; }"
        : "=r"(a) : "l"(p));
    return a;
}
__device__ __forceinline__ void ldsm_x4(uint32_t& r0, uint32_t& r1,
                                        uint32_t& r2, uint32_t& r3, uint32_t addr) {
    asm volatile("ldmatrix.sync.aligned.m8n8.x4.shared.b16 {%0,%1,%2,%3}, [%4];"
                 : "=r"(r0), "=r"(r1), "=r"(r2), "=r"(r3) : "r"(addr));
}
__device__ __forceinline__ void ldsm_x4t(uint32_t& r0, uint32_t& r1,
                                         uint32_t& r2, uint32_t& r3, uint32_t addr) {
    asm volatile("ldmatrix.sync.aligned.m8n8.x4.trans.shared.b16 {%0,%1,%2,%3}, [%4];"
                 : "=r"(r0), "=r"(r1), "=r"(r2), "=r"(r3) : "r"(addr));
}
__device__ __forceinline__ void mma16816(float* c, const uint32_t* a, const uint32_t* b) {
    asm volatile("mma.sync.aligned.m16n8k16.row.col.f32.bf16.bf16.f32 "
                 "{%0,%1,%2,%3}, {%4,%5,%6,%7}, {%8,%9}, {%0,%1,%2,%3};"
                 : "+f"(c[0]), "+f"(c[1]), "+f"(c[2]), "+f"(c[3])
                 : "r"(a[0]), "r"(a[1]), "r"(a[2]), "r"(a[3]),
                   "r"(b[0]), "r"(b[1]));
}
__device__ __forceinline__ void split2(float x, float y, uint32_t& hi, uint32_t& lo) {
    __nv_bfloat16 hx = __float2bfloat16_rn(x);
    __nv_bfloat16 hy = __float2bfloat16_rn(y);
    float lxf = x - __bfloat162float(hx);
    float lyf = y - __bfloat162float(hy);
    __nv_bfloat16 lx = __float2bfloat16_rn(lxf);
    __nv_bfloat16 ly = __float2bfloat16_rn(lyf);
    hi = ((uint32_t)__bfloat16_as_ushort(hy) << 16) | __bfloat16_as_ushort(hx);
    lo = ((uint32_t)__bfloat16_as_ushort(ly) << 16) | __bfloat16_as_ushort(lx);
}
__device__ __forceinline__ void cp16(uint32_t saddr, const void* g) {
    asm volatile("cp.async.cg.shared.global [%0], [%1], 16;"
                 :: "r"(saddr), "l"(g));
}
__device__ __forceinline__ void cp16_ca(uint32_t saddr, const void* g) {
    asm volatile("cp.async.ca.shared.global [%0], [%1], 16;"
                 :: "r"(saddr), "l"(g));
}
#define CP_COMMIT() asm volatile("cp.async.commit_group;" ::: "memory")
#define CP_WAIT0()  asm volatile("cp.async.wait_group 0;" ::: "memory")

// ---------------------------------------------------------------------------
// Fused split: all five fp32 tensors -> bf16 hi/lo in one launch.
// ---------------------------------------------------------------------------
#define SEG_H   (QROWS * DM)                 // 4194304
#define SEG_C   (SEG_H + KVROWS * DM)        // 12582912
#define SEG_WQ  (SEG_C + DM * DM)            // 13631488
#define SEG_WKV (SEG_WQ + 2 * DM * DM)       // 15728640
#define SEG_WO  (SEG_WKV + DM * DM)          // 16777216

__global__ __launch_bounds__(256) void split_all(
    const float* __restrict__ h, const float* __restrict__ c,
    const float* __restrict__ Wq, const float* __restrict__ Wkv,
    const float* __restrict__ Wo,
    ushort_t* __restrict__ hh, ushort_t* __restrict__ hl,
    ushort_t* __restrict__ ch, ushort_t* __restrict__ cl,
    ushort_t* __restrict__ Wqh, ushort_t* __restrict__ Wql,
    ushort_t* __restrict__ Wkvh, ushort_t* __restrict__ Wkvl,
    ushort_t* __restrict__ Woh, ushort_t* __restrict__ Wol)
{
    size_t idx = ((size_t)blockIdx.x * 256 + threadIdx.x) * 4;
    if (idx >= SEG_WO) return;
    const float* X; ushort_t *Xh, *Xl; size_t off;
    if      (idx < SEG_H)   { X = h;   Xh = hh;   Xl = hl;   off = 0; }
    else if (idx < SEG_C)   { X = c;   Xh = ch;   Xl = cl;   off = SEG_H; }
    else if (idx < SEG_WQ)  { X = Wq;  Xh = Wqh;  Xl = Wql;  off = SEG_C; }
    else if (idx < SEG_WKV) { X = Wkv; Xh = Wkvh; Xl = Wkvl; off = SEG_WQ; }
    else                    { X = Wo;  Xh = Woh;  Xl = Wol;  off = SEG_WKV; }
    size_t l = idx - off;
    float4 v = *(const float4*)(X + l);
    uint32_t h0, l0, h1, l1;
    split2(v.x, v.y, h0, l0);
    split2(v.z, v.w, h1, l1);
    uint2 hv; hv.x = h0; hv.y = h1;
    uint2 lv; lv.x = l0; lv.y = l1;
    *(uint2*)(Xh + l) = hv;
    *(uint2*)(Xl + l) = lv;
}

// ---------------------------------------------------------------------------
// GEMM core (NT): C = A[M,K] * B[N,K]^T, A/B pre-split hi/lo.
// CTA 128x128, BK=32, 256 threads (8 warps, warp tile 64x32),
// single-barrier 2-stage cp.async pipeline. A loads use .ca (co-resident CTA
// shares the same A rows -> L1 reuse); B uses .cg.
// SPLIT=1: outputs bf16 hi/lo (scaled). SPLIT=0: fp32 + residual.
// ---------------------------------------------------------------------------
#define ROWB  80
#define AREG  10240              // 128 rows * 80B
#define STAGE 40960              // Ah | Al | Bh | Bl
#define GEMM_SMEM (2*STAGE)      // 81920

template<int SPLIT>
__device__ __forceinline__ void gemm_core(
    const ushort_t* __restrict__ Ah_g, const ushort_t* __restrict__ Al_g,
    const ushort_t* __restrict__ Bh_g, const ushort_t* __restrict__ Bl_g,
    const float* __restrict__ R, float* __restrict__ C,
    ushort_t* __restrict__ Ch, ushort_t* __restrict__ Cl,
    float oscale, int N, int K, int m0, int n0, char* sm)
{
    const uint32_t sb = smem_u32(sm);
    const int tid = threadIdx.x;
    const int wid = tid >> 5, lane = tid & 31;
    const int wm = wid & 1, wn = wid >> 1;

    const int cid0 = tid * 2;

    float acc[4][4][4];
#pragma unroll
    for (int mi = 0; mi < 4; mi++)
#pragma unroll
        for (int nj = 0; nj < 4; nj++)
#pragma unroll
            for (int e = 0; e < 4; e++) acc[mi][nj][e] = 0.f;

    const int l8   = lane & 7;
    const int arow = ((lane >> 3) & 1) * 8 + l8;
    const int acol = ((lane >> 4) & 1) * 16;
    const int b4row = ((lane >> 4) & 1) * 8 + l8;
    const int b4col = ((lane >> 3) & 1) * 16;

    const int nchunks = K >> 5;

    auto issue = [&](int kc) {
        const int kk = kc << 5;
        const uint32_t sbase = sb + (uint32_t)(kc & 1) * STAGE;
#pragma unroll
        for (int u = 0; u < 2; u++) {
            int cid = cid0 + u;
            int row = cid >> 2, c16 = cid & 3;
            uint32_t so = sbase + (uint32_t)row * ROWB + c16 * 16;
            size_t ao = (size_t)(m0 + row) * K + kk + c16 * 8;
            size_t bo = (size_t)(n0 + row) * K + kk + c16 * 8;
            cp16_ca(so,          Ah_g + ao);
            cp16_ca(so +   AREG, Al_g + ao);
            cp16(so + 2*AREG, Bh_g + bo);
            cp16(so + 3*AREG, Bl_g + bo);
        }
        CP_COMMIT();
    };

    issue(0);

    for (int kc = 0; kc < nchunks; kc++) {
        CP_WAIT0();                       // stage kc landed (only group in flight)
        __syncthreads();                  // all threads done reading the buddy buffer
        if (kc + 1 < nchunks) issue(kc + 1);

        const uint32_t abase = sb + (uint32_t)(kc & 1) * STAGE;
        const uint32_t bbase = abase + 2 * AREG;
#pragma unroll
        for (int s = 0; s < 2; s++) {
            uint32_t bhf[4][2], blf[4][2];
#pragma unroll
            for (int njp = 0; njp < 2; njp++) {
                uint32_t baddr = bbase + (uint32_t)(wn*32 + njp*16 + b4row) * ROWB
                               + s*32 + b4col;
                ldsm_x4(bhf[2*njp][0], bhf[2*njp][1],
                        bhf[2*njp+1][0], bhf[2*njp+1][1], baddr);
                ldsm_x4(blf[2*njp][0], blf[2*njp][1],
                        blf[2*njp+1][0], blf[2*njp+1][1], baddr + AREG);
            }
            uint32_t af[4][4], afl[4][4];
#pragma unroll
            for (int mi = 0; mi < 4; mi++) {
                uint32_t aaddr = abase + (uint32_t)(wm*64 + mi*16 + arow) * ROWB
                               + s*32 + acol;
                ldsm_x4(af[mi][0], af[mi][1], af[mi][2], af[mi][3], aaddr);
                ldsm_x4(afl[mi][0], afl[mi][1], afl[mi][2], afl[mi][3], aaddr + AREG);
            }
#pragma unroll
            for (int mi = 0; mi < 4; mi++)
#pragma unroll
                for (int nj = 0; nj < 4; nj++)
                    mma16816(acc[mi][nj], af[mi], bhf[nj]);   // hi*hi
#pragma unroll
            for (int mi = 0; mi < 4; mi++)
#pragma unroll
                for (int nj = 0; nj < 4; nj++)
                    mma16816(acc[mi][nj], af[mi], blf[nj]);   // hi*lo
#pragma unroll
            for (int mi = 0; mi < 4; mi++)
#pragma unroll
                for (int nj = 0; nj < 4; nj++)
                    mma16816(acc[mi][nj], afl[mi], bhf[nj]);  // lo*hi
        }
    }

#pragma unroll
    for (int mi = 0; mi < 4; mi++) {
#pragma unroll
        for (int nj = 0; nj < 4; nj++) {
            int r0  = m0 + wm*64 + mi*16 + (lane >> 2);
            int col = n0 + wn*32 + nj*8 + (lane & 3) * 2;
            size_t o0 = (size_t)r0 * N + col;
            size_t o1 = (size_t)(r0 + 8) * N + col;
            if (SPLIT) {
                uint32_t h0, l0, h1, l1;
                split2(acc[mi][nj][0]*oscale, acc[mi][nj][1]*oscale, h0, l0);
                split2(acc[mi][nj][2]*oscale, acc[mi][nj][3]*oscale, h1, l1);
                *(uint32_t*)(Ch + o0) = h0;
                *(uint32_t*)(Cl + o0) = l0;
                *(uint32_t*)(Ch + o1) = h1;
                *(uint32_t*)(Cl + o1) = l1;
            } else {
                float2 v01, v23;
                v01.x = acc[mi][nj][0]; v01.y = acc[mi][nj][1];
                v23.x = acc[mi][nj][2]; v23.y = acc[mi][nj][3];
                float2 q0 = *(const float2*)(R + o0);
                float2 q1 = *(const float2*)(R + o1);
                v01.x += q0.x; v01.y += q0.y;
                v23.x += q1.x; v23.y += q1.y;
                *(float2*)(C + o0) = v01;
                *(float2*)(C + o1) = v23;
            }
        }
    }
}

// Fused Q+KV projection: 1-D grid of 1280 CTAs. KV tiles [0,1024), Q [1024,1280).
__global__ __launch_bounds__(256, 2) void mma_gemm_qkv(
    const ushort_t* __restrict__ hh, const ushort_t* __restrict__ hl,
    const ushort_t* __restrict__ Wqh, const ushort_t* __restrict__ Wql,
    const ushort_t* __restrict__ ch, const ushort_t* __restrict__ cl,
    const ushort_t* __restrict__ Wkvh, const ushort_t* __restrict__ Wkvl,
    ushort_t* __restrict__ Qh, ushort_t* __restrict__ Ql,
    ushort_t* __restrict__ KVh, ushort_t* __restrict__ KVl)
{
    extern __shared__ __align__(128) char sm[];
    int bid = blockIdx.x;
    if (bid < 1024) {
        int nt = bid & 15, mt = bid >> 4;       // KV: 16 x 64 tiles
        gemm_core<1>(ch, cl, Wkvh, Wkvl, nullptr, nullptr, KVh, KVl,
                     1.0f, 2*DM, DM, mt*128, nt*128, sm);
    } else {
        bid -= 1024;
        int nt = bid & 7, mt = bid >> 3;        // Q: 8 x 32 tiles
        gemm_core<1>(hh, hl, Wqh, Wql, nullptr, nullptr, Qh, Ql,
                     ATTN_SCALE, DM, DM, mt*128, nt*128, sm);
    }
}

// O projection (fp32 out + residual), classic 2-D grid.
__global__ __launch_bounds__(256, 2) void mma_gemm_o(
    const ushort_t* __restrict__ Ah_g, const ushort_t* __restrict__ Al_g,
    const ushort_t* __restrict__ Bh_g, const ushort_t* __restrict__ Bl_g,
    const float* __restrict__ R, float* __restrict__ C)
{
    extern __shared__ __align__(128) char sm[];
    gemm_core<0>(Ah_g, Al_g, Bh_g, Bl_g, R, C, nullptr, nullptr,
                 1.0f, DM, DM, blockIdx.y * 128, blockIdx.x * 128, sm);
}

// ---------------------------------------------------------------------------
// mma flash attention. Block: 256 queries x head x batch, 512 threads
// (16 warps, 16 q-rows each -> per-warp state identical to the 128-q version).
// 32 kv tiles of 64 keys, single-barrier cp.async pipeline.
// Halves KV L2 traffic vs 128-q CTAs.
// ---------------------------------------------------------------------------
#define AROW 144
#define QTILE 256
#define QH_OFF 0
#define QL_OFF (QTILE*AROW)                  // 36864
#define KVBUF_OFF (2*QTILE*AROW)             // 73728
#define KVBUF_SZ  36864
#define ATTN_SMEM (KVBUF_OFF + 2*KVBUF_SZ)   // 147456

__global__ __launch_bounds__(512, 1) void attn_mma(
    const ushort_t* __restrict__ Qh, const ushort_t* __restrict__ Ql,
    const ushort_t* __restrict__ KVh, const ushort_t* __restrict__ KVl,
    ushort_t* __restrict__ AVh, ushort_t* __restrict__ AVl)
{
    extern __shared__ __align__(128) char sm[];
    const uint32_t sb = smem_u32(sm);
    const int qt = blockIdx.x, n = blockIdx.y, b = blockIdx.z;
    const int tid = threadIdx.x;
    const int wid = tid >> 5, lane = tid & 31;

    const int l8   = lane & 7;
    const int arow = ((lane >> 3) & 1) * 8 + l8;
    const int acol = ((lane >> 4) & 1) * 16;
    const int b4row = ((lane >> 4) & 1) * 8 + l8;
    const int b4col = ((lane >> 3) & 1) * 16;

    // issue KV tile jt into its double buffer (512 chunks, 1 per thread)
    auto issue_kv = [&](int jt) {
        uint32_t bufn = sb + KVBUF_OFF + (uint32_t)(jt & 1) * KVBUF_SZ;
        int cid = tid;
        int row = cid >> 3, c16 = cid & 7;
        size_t gr = (size_t)(jt*64 + row) * BB + b;
        size_t ko = gr * (2*DM) + n * DH + c16 * 8;
        size_t vo = ko + DM;
        uint32_t so = bufn + row*AROW + c16*16;
        cp16(so,         KVh + ko);
        cp16(so +  9216, KVl + ko);
        cp16(so + 18432, KVh + vo);
        cp16(so + 27648, KVl + vo);
        CP_COMMIT();
    };

    // prologue: Q tile (256 rows x 8 chunks x {h,l}) + KV tile 0
    {
        int c0 = tid * 4;
#pragma unroll
        for (int u = 0; u < 4; u++) {
            int cid = c0 + u;                 // 0..2047
            int row = cid >> 3, c16 = cid & 7;
            size_t grow = (size_t)(qt*QTILE + row) * BB + b;
            size_t goff = grow * DM + n * DH + c16 * 8;
            cp16(sb + QH_OFF + row*AROW + c16*16, Qh + goff);
            cp16(sb + QL_OFF + row*AROW + c16*16, Ql + goff);
        }
    }
    issue_kv(0);

    float o[8][4];
#pragma unroll
    for (int dj = 0; dj < 8; dj++)
#pragma unroll
        for (int e = 0; e < 4; e++) o[dj][e] = 0.f;
    float m0 = -1e30f, m1 = -1e30f, lac0 = 0.f, lac1 = 0.f;

    for (int jt = 0; jt < KVL/64; jt++) {
        CP_WAIT0();
        __syncthreads();
        if (jt + 1 < KVL/64) issue_kv(jt + 1);

        const uint32_t kb = sb + KVBUF_OFF + (uint32_t)(jt & 1) * KVBUF_SZ;
        const uint32_t vb = kb + 18432;

        float s[8][4];
#pragma unroll
        for (int nj = 0; nj < 8; nj++)
#pragma unroll
            for (int e = 0; e < 4; e++) s[nj][e] = 0.f;

#pragma unroll
        for (int ks = 0; ks < 4; ks++) {
            uint32_t qf[4], qfl[4];
            uint32_t qaddr = sb + QH_OFF + (uint32_t)(wid*16 + arow)*AROW + ks*32 + acol;
            ldsm_x4(qf[0], qf[1], qf[2], qf[3], qaddr);
            ldsm_x4(qfl[0], qfl[1], qfl[2], qfl[3], qaddr + (QL_OFF - QH_OFF));
#pragma unroll
            for (int njp = 0; njp < 4; njp++) {
                uint32_t kh[4], kl[4];
                uint32_t kaddr = kb + (uint32_t)(njp*16 + b4row)*AROW + ks*32 + b4col;
                ldsm_x4(kh[0], kh[1], kh[2], kh[3], kaddr);
                ldsm_x4(kl[0], kl[1], kl[2], kl[3], kaddr + 9216);
                mma16816(s[2*njp],   qf,  kh);
                mma16816(s[2*njp+1], qf,  kh + 2);
                mma16816(s[2*njp],   qf,  kl);
                mma16816(s[2*njp+1], qf,  kl + 2);
                mma16816(s[2*njp],   qfl, kh);
                mma16816(s[2*njp+1], qfl, kh + 2);
            }
        }

        float rmax0 = -1e30f, rmax1 = -1e30f;
#pragma unroll
        for (int nj = 0; nj < 8; nj++) {
            rmax0 = fmaxf(rmax0, fmaxf(s[nj][0], s[nj][1]));
            rmax1 = fmaxf(rmax1, fmaxf(s[nj][2], s[nj][3]));
        }
        rmax0 = fmaxf(rmax0, __shfl_xor_sync(0xffffffffu, rmax0, 1));
        rmax0 = fmaxf(rmax0, __shfl_xor_sync(0xffffffffu, rmax0, 2));
        rmax1 = fmaxf(rmax1, __shfl_xor_sync(0xffffffffu, rmax1, 1));
        rmax1 = fmaxf(rmax1, __shfl_xor_sync(0xffffffffu, rmax1, 2));
        float mn0 = fmaxf(m0, rmax0), mn1 = fmaxf(m1, rmax1);
        float fc0 = __expf(m0 - mn0), fc1 = __expf(m1 - mn1);
        m0 = mn0; m1 = mn1;
        float sum0 = 0.f, sum1 = 0.f;
#pragma unroll
        for (int nj = 0; nj < 8; nj++) {
            float p0 = __expf(s[nj][0] - mn0);
            float p1 = __expf(s[nj][1] - mn0);
            float p2 = __expf(s[nj][2] - mn1);
            float p3 = __expf(s[nj][3] - mn1);
            s[nj][0] = p0; s[nj][1] = p1; s[nj][2] = p2; s[nj][3] = p3;
            sum0 += p0 + p1; sum1 += p2 + p3;
        }
        sum0 += __shfl_xor_sync(0xffffffffu, sum0, 1);
        sum0 += __shfl_xor_sync(0xffffffffu, sum0, 2);
        sum1 += __shfl_xor_sync(0xffffffffu, sum1, 1);
        sum1 += __shfl_xor_sync(0xffffffffu, sum1, 2);
        lac0 = lac0 * fc0 + sum0;
        lac1 = lac1 * fc1 + sum1;
#pragma unroll
        for (int dj = 0; dj < 8; dj++) {
            o[dj][0] *= fc0; o[dj][1] *= fc0;
            o[dj][2] *= fc1; o[dj][3] *= fc1;
        }

#pragma unroll
        for (int ks = 0; ks < 4; ks++) {
            uint32_t ah[4], al[4];
            split2(s[2*ks][0],   s[2*ks][1],   ah[0], al[0]);
            split2(s[2*ks][2],   s[2*ks][3],   ah[1], al[1]);
            split2(s[2*ks+1][0], s[2*ks+1][1], ah[2], al[2]);
            split2(s[2*ks+1][2], s[2*ks+1][3], ah[3], al[3]);
#pragma unroll
            for (int djp = 0; djp < 4; djp++) {
                int dj = djp * 2;
                int mm = lane >> 3;
                uint32_t vaddr = vb
                    + (uint32_t)(ks*16 + (mm & 1)*8 + l8) * AROW
                    + (uint32_t)(dj + (mm >> 1)) * 16;
                uint32_t vh[4], vl[4];
                ldsm_x4t(vh[0], vh[1], vh[2], vh[3], vaddr);
                ldsm_x4t(vl[0], vl[1], vl[2], vl[3], vaddr + 9216);
                mma16816(o[dj],   ah, vh);
                mma16816(o[dj+1], ah, vh + 2);
                mma16816(o[dj],   ah, vl);
                mma16816(o[dj+1], ah, vl + 2);
                mma16816(o[dj],   al, vh);
                mma16816(o[dj+1], al, vh + 2);
            }
        }
    }

    // ---- epilogue: divide by l, split to bf16 hi/lo ----
    float inv0 = 1.f / lac0, inv1 = 1.f / lac1;
    int g = lane >> 2;
    size_t gr0 = ((size_t)(qt*QTILE + wid*16 + g)) * BB + b;
    size_t gr1 = gr0 + (size_t)8 * BB;
    int colb = n * DH + (lane & 3) * 2;
#pragma unroll
    for (int dj = 0; dj < 8; dj++) {
        uint32_t h0, l0, h1, l1;
        split2(o[dj][0] * inv0, o[dj][1] * inv0, h0, l0);
        split2(o[dj][2] * inv1, o[dj][3] * inv1, h1, l1);
        *(uint32_t*)(AVh + gr0 * DM + colb + dj*8) = h0;
        *(uint32_t*)(AVl + gr0 * DM + colb + dj*8) = l0;
        *(uint32_t*)(AVh + gr1 * DM + colb + dj*8) = h1;
        *(uint32_t*)(AVl + gr1 * DM + colb + dj*8) = l1;
    }
}

// ---------------------------------------------------------------------------
// LayerNorm over rows of 1024.
// ---------------------------------------------------------------------------
__global__ __launch_bounds__(256) void ln_kernel(
    const float* __restrict__ Y, const float* __restrict__ gamma,
    const float* __restrict__ beta, float* __restrict__ out)
{
    __shared__ float red1[8];
    __shared__ float red2[8];
    const int row = blockIdx.x, tid = threadIdx.x;
    const float* y = Y + (size_t)row * DM;
    float v[4];
#pragma unroll
    for (int u = 0; u < 4; u++) v[u] = y[tid + u*256];

    float s = v[0] + v[1] + v[2] + v[3];
#pragma unroll
    for (int m = 16; m; m >>= 1) s += __shfl_xor_sync(0xffffffffu, s, m);
    if ((tid & 31) == 0) red1[tid >> 5] = s;
    __syncthreads();
    float tot = 0.f;
#pragma unroll
    for (int w = 0; w < 8; w++) tot += red1[w];
    float mu = tot * (1.f / DM);

    float q = 0.f;
#pragma unroll
    for (int u = 0; u < 4; u++) { float d = v[u] - mu; q += d * d; }
#pragma unroll
    for (int m = 16; m; m >>= 1) q += __shfl_xor_sync(0xffffffffu, q, m);
    if ((tid & 31) == 0) red2[tid >> 5] = q;
    __syncthreads();
    float qtot = 0.f;
#pragma unroll
    for (int w = 0; w < 8; w++) qtot += red2[w];
    float inv = rsqrtf(qtot * (1.f / DM) + 1e-5f);

#pragma unroll
    for (int u = 0; u < 4; u++) {
        int cix = tid + u*256;
        out[(size_t)row * DM + cix] = (v[u] - mu) * inv * gamma[cix] + beta[cix];
    }
}

// ---------------------------------------------------------------------------
extern "C" void kernel_launch(void* const* d_in, const int* in_sizes, int n_in,
                              void* d_out, int out_size)
{
    const float* h     = (const float*)d_in[0];
    const float* c     = (const float*)d_in[1];
    const float* Wq    = (const float*)d_in[2];
    const float* Wkv   = (const float*)d_in[3];
    const float* Wo    = (const float*)d_in[4];
    const float* gamma = (const float*)d_in[5];
    const float* beta  = (const float*)d_in[6];
    float* out = (float*)d_out;

    ushort_t *hh, *hl, *ch, *cl, *Wqh, *Wql, *Wkvh, *Wkvl, *Woh, *Wol;
    ushort_t *Qh, *Ql, *KVh, *KVl, *AVh, *AVl;
    float *Yb;
    cudaGetSymbolAddress((void**)&hh,   g_hh);
    cudaGetSymbolAddress((void**)&hl,   g_hl);
    cudaGetSymbolAddress((void**)&ch,   g_ch);
    cudaGetSymbolAddress((void**)&cl,   g_cl);
    cudaGetSymbolAddress((void**)&Wqh,  g_Wqh);
    cudaGetSymbolAddress((void**)&Wql,  g_Wql);
    cudaGetSymbolAddress((void**)&Wkvh, g_Wkvh);
    cudaGetSymbolAddress((void**)&Wkvl, g_Wkvl);
    cudaGetSymbolAddress((void**)&Woh,  g_Woh);
    cudaGetSymbolAddress((void**)&Wol,  g_Wol);
    cudaGetSymbolAddress((void**)&Qh,   g_Qh);
    cudaGetSymbolAddress((void**)&Ql,   g_Ql);
    cudaGetSymbolAddress((void**)&KVh,  g_KVh);
    cudaGetSymbolAddress((void**)&KVl,  g_KVl);
    cudaGetSymbolAddress((void**)&AVh,  g_AVh);
    cudaGetSymbolAddress((void**)&AVl,  g_AVl);
    cudaGetSymbolAddress((void**)&Yb,   g_Y);

    cudaFuncSetAttribute(mma_gemm_qkv,
                         cudaFuncAttributeMaxDynamicSharedMemorySize, GEMM_SMEM);
    cudaFuncSetAttribute(mma_gemm_o,
                         cudaFuncAttributeMaxDynamicSharedMemorySize, GEMM_SMEM);
    cudaFuncSetAttribute(attn_mma,
                         cudaFuncAttributeMaxDynamicSharedMemorySize, ATTN_SMEM);

    // ---- fused pre-split of all fp32 inputs ----
    split_all<<<SEG_WO/1024, 256>>>(h, c, Wq, Wkv, Wo,
                                    hh, hl, ch, cl, Wqh, Wql,
                                    Wkvh, Wkvl, Woh, Wol);

    // ---- fused Q + KV projections (1280 CTAs) ----
    mma_gemm_qkv<<<1280, 256, GEMM_SMEM>>>(hh, hl, Wqh, Wql,
                                           ch, cl, Wkvh, Wkvl,
                                           Qh, Ql, KVh, KVl);

    // attention -> AV split (256-query CTAs)      [4096 x 1024]
    attn_mma<<<dim3(QL/QTILE, NH, BB), 512, ATTN_SMEM>>>(Qh, Ql, KVh, KVl, AVh, AVl);

    // Y = AV @ Wo^T + h                           [4096 x 1024]
    mma_gemm_o<<<dim3(DM/128, QROWS/128), 256, GEMM_SMEM>>>(
        AVh, AVl, Woh, Wol, h, Yb);

    // out = LN(Y)
    ln_kernel<<<QROWS, 256>>>(Yb, gamma, beta, out);
}